// round 1
// baseline (speedup 1.0000x reference)
#include <cuda_runtime.h>
#include <math.h>

#define B_ 32
#define S_ 512
#define F_ 512
#define T_ 1024

// Scratch (allocation-free per harness rules). G reuses g_aux.
__device__ float g_aux [(size_t)B_ * S_ * T_];   // aux = W_b @ z_h, later G
__device__ float g_aux2[(size_t)B_ * F_ * T_];   // W_v @ z_h
__device__ float g_aux3[(size_t)B_ * F_ * T_];   // W_q @ z_r
__device__ float g_logit[B_ * T_];               // w_hq @ H_q

// ---------------------------------------------------------------------------
// Generic batched tiled GEMM: D[b] = epilogue(A[b] @ B[b])
//   TA: A element (m,k) at Ap[k*lda + m]  (else Ap[m*lda + k])
//   TB: B element (k,n) at Bp[n*ldb + k]  (else Bp[k*ldb + n])
//   EPI 0: D = acc
//   EPI 1: D = tanh(acc)
//   EPI 2: D = wv[m] * tanh(acc + E[m*ldd + n])
// Dims must be multiples of tile sizes (they are: 512/1024, K 512/1024).
// ---------------------------------------------------------------------------
#define BM 128
#define BN 128
#define BK 16
#define SPAD 132   // smem row stride (pad vs 128 to soften store conflicts)

template <bool TA, bool TB, int EPI>
__global__ __launch_bounds__(256, 2)
void gemm_k(const float* __restrict__ Ap, const float* __restrict__ Bp,
            float* __restrict__ Dp, const float* __restrict__ Ep,
            const float* __restrict__ wv,
            int M, int N, int K, int lda, int ldb, int ldd,
            long sA, long sB, long sD, long sE)
{
    __shared__ float As[BK][SPAD];
    __shared__ float Bs[BK][SPAD];

    const int b = blockIdx.z;
    const float* A = Ap + (size_t)b * sA;
    const float* Bm = Bp + (size_t)b * sB;
    float* D = Dp + (size_t)b * sD;
    const float* E = (EPI == 2) ? (Ep + (size_t)b * sE) : nullptr;

    const int m0 = blockIdx.y * BM;
    const int n0 = blockIdx.x * BN;
    const int tid = threadIdx.x;
    const int tx = tid & 15;        // column group (8 cols)
    const int ty = tid >> 4;        // row group    (8 rows)

    float acc[8][8];
#pragma unroll
    for (int i = 0; i < 8; i++)
#pragma unroll
        for (int j = 0; j < 8; j++) acc[i][j] = 0.0f;

    for (int k0 = 0; k0 < K; k0 += BK) {
        // --- load A tile into As[k][m] ---
#pragma unroll
        for (int i = 0; i < 8; i++) {
            int idx = tid + i * 256;
            if (TA) {
                int m = idx & (BM - 1), kk = idx >> 7;
                As[kk][m] = A[(size_t)(k0 + kk) * lda + (m0 + m)];
            } else {
                int kk = idx & (BK - 1), m = idx >> 4;
                As[kk][m] = A[(size_t)(m0 + m) * lda + (k0 + kk)];
            }
        }
        // --- load B tile into Bs[k][n] ---
#pragma unroll
        for (int i = 0; i < 8; i++) {
            int idx = tid + i * 256;
            if (TB) {
                int kk = idx & (BK - 1), n = idx >> 4;
                Bs[kk][n] = Bm[(size_t)(n0 + n) * ldb + (k0 + kk)];
            } else {
                int n = idx & (BN - 1), kk = idx >> 7;
                Bs[kk][n] = Bm[(size_t)(k0 + kk) * ldb + (n0 + n)];
            }
        }
        __syncthreads();

#pragma unroll
        for (int kk = 0; kk < BK; kk++) {
            float4 a0 = *(const float4*)&As[kk][ty * 8];
            float4 a1 = *(const float4*)&As[kk][ty * 8 + 4];
            float4 b0 = *(const float4*)&Bs[kk][tx * 8];
            float4 b1 = *(const float4*)&Bs[kk][tx * 8 + 4];
            float ar[8] = {a0.x, a0.y, a0.z, a0.w, a1.x, a1.y, a1.z, a1.w};
            float br[8] = {b0.x, b0.y, b0.z, b0.w, b1.x, b1.y, b1.z, b1.w};
#pragma unroll
            for (int i = 0; i < 8; i++)
#pragma unroll
                for (int j = 0; j < 8; j++)
                    acc[i][j] = fmaf(ar[i], br[j], acc[i][j]);
        }
        __syncthreads();
    }

    // --- epilogue + store (vectorized) ---
#pragma unroll
    for (int i = 0; i < 8; i++) {
        int m = m0 + ty * 8 + i;
        float* drow = D + (size_t)m * ldd + n0 + tx * 8;
        float v[8];
        if (EPI == 0) {
#pragma unroll
            for (int j = 0; j < 8; j++) v[j] = acc[i][j];
        } else if (EPI == 1) {
#pragma unroll
            for (int j = 0; j < 8; j++) v[j] = tanhf(acc[i][j]);
        } else {
            const float* erow = E + (size_t)m * ldd + n0 + tx * 8;
            float w = wv[m];
#pragma unroll
            for (int j = 0; j < 8; j++) v[j] = w * tanhf(acc[i][j] + erow[j]);
        }
        *(float4*)(drow)     = make_float4(v[0], v[1], v[2], v[3]);
        *(float4*)(drow + 4) = make_float4(v[4], v[5], v[6], v[7]);
    }
}

// logits[b,t] = sum_f G[b,f,t]
__global__ void col_reduce_k(const float* __restrict__ G)
{
    int t = blockIdx.x * blockDim.x + threadIdx.x;
    int b = blockIdx.y;
    const float* g = G + (size_t)b * F_ * T_ + t;
    float acc = 0.0f;
#pragma unroll 8
    for (int f = 0; f < F_; f++) acc += g[(size_t)f * T_];
    g_logit[b * T_ + t] = acc;
}

// a_q[b,:] = softmax(logits[b,:]) over T
__global__ void softmax_k(float* __restrict__ aq)
{
    __shared__ float sm[256];
    int b = blockIdx.x;
    int tid = threadIdx.x;
    const float* lg = g_logit + b * T_;
    float v[4];
    float vmax = -1e30f;
#pragma unroll
    for (int i = 0; i < 4; i++) { v[i] = lg[tid + i * 256]; vmax = fmaxf(vmax, v[i]); }
    sm[tid] = vmax; __syncthreads();
    for (int s = 128; s > 0; s >>= 1) {
        if (tid < s) sm[tid] = fmaxf(sm[tid], sm[tid + s]);
        __syncthreads();
    }
    vmax = sm[0]; __syncthreads();
    float lsum = 0.0f;
#pragma unroll
    for (int i = 0; i < 4; i++) { v[i] = expf(v[i] - vmax); lsum += v[i]; }
    sm[tid] = lsum; __syncthreads();
    for (int s = 128; s > 0; s >>= 1) {
        if (tid < s) sm[tid] += sm[tid + s];
        __syncthreads();
    }
    float inv = 1.0f / sm[0];
#pragma unroll
    for (int i = 0; i < 4; i++) aq[b * T_ + tid + i * 256] = v[i] * inv;
}

// attn[b,s] = sum_t z_r[b,s,t] * a_q[b,t]   (one warp per (b,s))
__global__ void attn_k(const float* __restrict__ zr, const float* __restrict__ aq,
                       float* __restrict__ out)
{
    int gwarp = (blockIdx.x * blockDim.x + threadIdx.x) >> 5;
    int lane = threadIdx.x & 31;
    int b = gwarp >> 9;          // / S_
    int s = gwarp & (S_ - 1);
    const float* z = zr + ((size_t)b * S_ + s) * T_;
    const float* a = aq + b * T_;
    float acc = 0.0f;
#pragma unroll 4
    for (int t = lane; t < T_; t += 32) acc += z[t] * a[t];
#pragma unroll
    for (int o = 16; o > 0; o >>= 1) acc += __shfl_xor_sync(0xFFFFFFFFu, acc, o);
    if (lane == 0) out[b * S_ + s] = acc;
}

extern "C" void kernel_launch(void* const* d_in, const int* in_sizes, int n_in,
                              void* d_out, int out_size)
{
    const float* zr  = (const float*)d_in[0];   // z_robot [B,S,T]
    const float* zh  = (const float*)d_in[1];   // z_human [B,S,T]
    const float* Wb  = (const float*)d_in[2];   // [S,S]
    const float* Wq  = (const float*)d_in[3];   // [F,S]
    const float* Wv  = (const float*)d_in[4];   // [F,S]
    const float* whq = (const float*)d_in[5];   // [1,F]

    float* out  = (float*)d_out;
    float* attn = out;                       // [B,S]
    float* aq   = out + B_ * S_;             // [B,T]
    float* Cmat = out + B_ * S_ + B_ * T_;   // [B,T,T]

    float *aux, *aux2, *aux3;
    cudaGetSymbolAddress((void**)&aux,  g_aux);
    cudaGetSymbolAddress((void**)&aux2, g_aux2);
    cudaGetSymbolAddress((void**)&aux3, g_aux3);

    const long ST = (long)S_ * T_;
    const long FT = (long)F_ * T_;
    const long TT2 = (long)T_ * T_;

    // 1. aux = W_b @ z_human    [S,T] per batch
    gemm_k<false, false, 0><<<dim3(T_ / BN, S_ / BM, B_), 256>>>(
        Wb, zh, aux, nullptr, nullptr, S_, T_, S_, S_, T_, T_, 0, ST, ST, 0);

    // 2. C = tanh(z_robot^T @ aux)   [T,T] per batch  -> directly into d_out
    gemm_k<true, false, 1><<<dim3(T_ / BN, T_ / BM, B_), 256>>>(
        zr, aux, Cmat, nullptr, nullptr, T_, T_, S_, T_, T_, T_, ST, ST, TT2, 0);

    // 3. aux2 = W_v @ z_human
    gemm_k<false, false, 0><<<dim3(T_ / BN, F_ / BM, B_), 256>>>(
        Wv, zh, aux2, nullptr, nullptr, F_, T_, S_, S_, T_, T_, 0, ST, FT, 0);

    // 4. aux3 = W_q @ z_robot
    gemm_k<false, false, 0><<<dim3(T_ / BN, F_ / BM, B_), 256>>>(
        Wq, zr, aux3, nullptr, nullptr, F_, T_, S_, S_, T_, T_, 0, ST, FT, 0);

    // 5. G = w_hq[f] * tanh(aux3 + aux2 @ C^T)   (H_q never materialized)
    gemm_k<false, true, 2><<<dim3(T_ / BN, F_ / BM, B_), 256>>>(
        aux2, Cmat, aux /* G reuses aux */, aux3, whq,
        F_, T_, T_, T_, T_, T_, FT, TT2, FT, FT);

    // 6. logits = sum_f G
    col_reduce_k<<<dim3(T_ / 256, B_), 256>>>(aux);

    // 7. a_q = softmax(logits)  -> d_out
    softmax_k<<<B_, 256>>>(aq);

    // 8. attn = z_robot @ a_q^T -> d_out
    attn_k<<<(B_ * S_ * 32) / 256, 256>>>(zr, aq, attn);
}

// round 3
// speedup vs baseline: 1.5361x; 1.5361x over previous
#include <cuda_runtime.h>
#include <cuda_bf16.h>
#include <cstdint>
#include <math.h>

#define B_ 32
#define S_ 512
#define F_ 512
#define T_ 1024

#define BM 128
#define BN 128
#define BK 32
// smem: per tile 128 rows x (32+8) bf16 = 80B row stride, 10240B per tile.
// 4 tiles (Ahi, Alo, Bhi, Blo) per stage, 2 stages.
#define TILE_B   10240
#define STAGE_B  (4 * TILE_B)
#define GEMM_SMEM (2 * STAGE_B)
#define LDS_ROW  80   // bytes per smem row

// ---------------- scratch (allocation-free) ----------------
__device__ __nv_bfloat16 g_zhT_hi[(size_t)B_*T_*S_];
__device__ __nv_bfloat16 g_zhT_lo[(size_t)B_*T_*S_];
__device__ __nv_bfloat16 g_zrT_hi[(size_t)B_*T_*S_];
__device__ __nv_bfloat16 g_zrT_lo[(size_t)B_*T_*S_];
__device__ __nv_bfloat16 g_auxT_hi[(size_t)B_*T_*S_];
__device__ __nv_bfloat16 g_auxT_lo[(size_t)B_*T_*S_];
__device__ __nv_bfloat16 g_C_hi[(size_t)B_*T_*T_];
__device__ __nv_bfloat16 g_C_lo[(size_t)B_*T_*T_];
__device__ __nv_bfloat16 g_a2_hi[(size_t)B_*F_*T_];
__device__ __nv_bfloat16 g_a2_lo[(size_t)B_*F_*T_];
__device__ float g_a3[(size_t)B_*F_*T_];
__device__ float g_G [(size_t)B_*F_*T_];
__device__ __nv_bfloat16 g_Wb_hi[S_*S_], g_Wb_lo[S_*S_];
__device__ __nv_bfloat16 g_Wq_hi[F_*S_], g_Wq_lo[F_*S_];
__device__ __nv_bfloat16 g_Wv_hi[F_*S_], g_Wv_lo[F_*S_];
__device__ float g_logit[B_*T_];

// ---------------- helpers ----------------
static __device__ __forceinline__ uint32_t s2u(const void* p){
    uint32_t a;
    asm("{ .reg .u64 t; cvta.to.shared.u64 t, %1; cvt.u32.u64 %0, t; }" : "=r"(a) : "l"(p));
    return a;
}
static __device__ __forceinline__ void cp16(uint32_t dst, const void* src){
    asm volatile("cp.async.cg.shared.global [%0], [%1], 16;" :: "r"(dst), "l"(src) : "memory");
}
static __device__ __forceinline__ void cp_commit(){
    asm volatile("cp.async.commit_group;" ::: "memory");
}
static __device__ __forceinline__ void ldm_x4(uint32_t& r0, uint32_t& r1, uint32_t& r2, uint32_t& r3, uint32_t a){
    asm volatile("ldmatrix.sync.aligned.m8n8.x4.shared.b16 {%0,%1,%2,%3}, [%4];"
                 : "=r"(r0), "=r"(r1), "=r"(r2), "=r"(r3) : "r"(a));
}
static __device__ __forceinline__ void mma16816(float* d, const uint32_t* a, const uint32_t* b){
    asm volatile("mma.sync.aligned.m16n8k16.row.col.f32.bf16.bf16.f32 "
                 "{%0,%1,%2,%3}, {%4,%5,%6,%7}, {%8,%9}, {%0,%1,%2,%3};"
                 : "+f"(d[0]), "+f"(d[1]), "+f"(d[2]), "+f"(d[3])
                 : "r"(a[0]), "r"(a[1]), "r"(a[2]), "r"(a[3]), "r"(b[0]), "r"(b[1]));
}

enum { EPI_NONE = 0, EPI_HILO = 1, EPI_TANH_HILO = 2, EPI_WG = 3 };

// ---------------------------------------------------------------------------
// bf16 mma.sync GEMM with 3-term hi/lo compensation.
// D[b][m][n] = epi( sum_k (Ahi+Alo)[m][k]*(Bhi+Blo)[n][k] )   (lo*lo dropped)
// A,B row-major, K contiguous (row stride = K). Output row-major, ld = N.
// ---------------------------------------------------------------------------
template <int EPI>
__global__ __launch_bounds__(256)
void mma_gemm(const __nv_bfloat16* __restrict__ Ahi, const __nv_bfloat16* __restrict__ Alo,
              const __nv_bfloat16* __restrict__ Bhi, const __nv_bfloat16* __restrict__ Blo,
              float* __restrict__ Dout,
              __nv_bfloat16* __restrict__ Dhi, __nv_bfloat16* __restrict__ Dlo,
              const float* __restrict__ Eadd, const float* __restrict__ wv,
              int M, int N, int K, long sA, long sB, long sD, long sE)
{
    extern __shared__ char smem[];
    const uint32_t sb = s2u(smem);
    const int tid = threadIdx.x;
    const int wid = tid >> 5, lane = tid & 31;
    const int b = blockIdx.z;
    const int m0 = blockIdx.y * BM, n0 = blockIdx.x * BN;

    const __nv_bfloat16* srcA_hi = Ahi + (size_t)b * sA;
    const __nv_bfloat16* srcA_lo = Alo + (size_t)b * sA;
    const __nv_bfloat16* srcB_hi = Bhi + (size_t)b * sB;
    const __nv_bfloat16* srcB_lo = Blo + (size_t)b * sB;

    // loader geometry: 2048 16B units per stage (4 tiles x 512), 8 per thread
    const __nv_bfloat16* gsrc[8];
    uint32_t sdst[8];
#pragma unroll
    for (int u = 0; u < 8; u++) {
        int unit = tid + u * 256;
        int t = unit >> 9;              // tile 0..3
        int r = (unit >> 2) & 127;      // row 0..127
        int c = unit & 3;               // 16B chunk within 64B row
        const __nv_bfloat16* base =
            (t == 0) ? srcA_hi : (t == 1) ? srcA_lo : (t == 2) ? srcB_hi : srcB_lo;
        int row0 = (t < 2) ? m0 : n0;
        gsrc[u] = base + (size_t)(row0 + r) * K + c * 8;
        sdst[u] = sb + t * TILE_B + r * LDS_ROW + c * 16;
    }

    float acc[4][4][4];
#pragma unroll
    for (int i = 0; i < 4; i++)
#pragma unroll
        for (int j = 0; j < 4; j++)
#pragma unroll
            for (int q = 0; q < 4; q++) acc[i][j][q] = 0.0f;

    const int wm = (wid >> 2) * 64;      // warp m offset (0/64)
    const int wn = (wid & 3) * 32;       // warp n offset (0/32/64/96)

    // ldmatrix smem addresses (stage-0 base; add stage offset per iter)
    // A: per m-tile, row = wm + mf*16 + (lane&15), col halves by lane>>4
    uint32_t a_addr[4];
#pragma unroll
    for (int mf = 0; mf < 4; mf++) {
        int row = wm + mf * 16 + (lane & 15);
        int colb = (lane >> 4) * 16;     // 8 bf16 = 16B
        a_addr[mf] = sb + row * LDS_ROW + colb;
    }
    // B: x4 covers two n8 tiles: lanes0-7: n+0..7 k0 | 8-15: n+0..7 k8 | 16-23: n+8..15 k0 | 24-31: n+8..15 k8
    uint32_t b_addr[2];
#pragma unroll
    for (int nt = 0; nt < 2; nt++) {
        int row = wn + nt * 16 + (lane & 7) + ((lane & 16) >> 1);
        int colb = ((lane >> 3) & 1) * 16;
        b_addr[nt] = sb + row * LDS_ROW + colb;
    }

    const int NC = K / BK;

    // prologue: stage 0
#pragma unroll
    for (int u = 0; u < 8; u++) cp16(sdst[u], gsrc[u]);
    cp_commit();

    for (int i = 0; i < NC; i++) {
        if (i + 1 < NC) {
            const int buf = (i + 1) & 1;
            const int koff = (i + 1) * BK;
#pragma unroll
            for (int u = 0; u < 8; u++) cp16(sdst[u] + buf * STAGE_B, gsrc[u] + koff);
            cp_commit();
            asm volatile("cp.async.wait_group 1;" ::: "memory");
        } else {
            asm volatile("cp.async.wait_group 0;" ::: "memory");
        }
        __syncthreads();

        const uint32_t stg = (i & 1) * STAGE_B;
#pragma unroll
        for (int ks = 0; ks < 2; ks++) {
            const uint32_t kb = stg + ks * 32;   // 16 bf16 = 32B
            // B fragments (hi & lo), 4 n-tiles
            uint32_t bh[4][2], bl[4][2];
#pragma unroll
            for (int nt = 0; nt < 2; nt++) {
                ldm_x4(bh[nt*2][0], bh[nt*2][1], bh[nt*2+1][0], bh[nt*2+1][1],
                       b_addr[nt] + 2 * TILE_B + kb);
                ldm_x4(bl[nt*2][0], bl[nt*2][1], bl[nt*2+1][0], bl[nt*2+1][1],
                       b_addr[nt] + 3 * TILE_B + kb);
            }
#pragma unroll
            for (int mf = 0; mf < 4; mf++) {
                uint32_t ah[4], al[4];
                ldm_x4(ah[0], ah[1], ah[2], ah[3], a_addr[mf] + kb);
                ldm_x4(al[0], al[1], al[2], al[3], a_addr[mf] + TILE_B + kb);
#pragma unroll
                for (int nf = 0; nf < 4; nf++) {
                    mma16816(acc[mf][nf], ah, bh[nf]);
                    mma16816(acc[mf][nf], ah, bl[nf]);
                    mma16816(acc[mf][nf], al, bh[nf]);
                }
            }
        }
        __syncthreads();
    }

    // ---- epilogue ----
    const int g = lane >> 2, tg = lane & 3;
#pragma unroll
    for (int mf = 0; mf < 4; mf++) {
#pragma unroll
        for (int h = 0; h < 2; h++) {
            const int row = m0 + wm + mf * 16 + g + h * 8;
            float w = 0.0f;
            if (EPI == EPI_WG) w = wv[row];
            const size_t rowoff = (size_t)b * sD + (size_t)row * N;
#pragma unroll
            for (int nf = 0; nf < 4; nf++) {
                const int col = n0 + wn + nf * 8 + tg * 2;
                float d0 = acc[mf][nf][h * 2 + 0];
                float d1 = acc[mf][nf][h * 2 + 1];
                if (EPI == EPI_NONE) {
                    *(float2*)(Dout + rowoff + col) = make_float2(d0, d1);
                } else if (EPI == EPI_WG) {
                    const float2 e = *(const float2*)(Eadd + (size_t)b * sE + (size_t)row * N + col);
                    *(float2*)(Dout + rowoff + col) =
                        make_float2(w * tanhf(d0 + e.x), w * tanhf(d1 + e.y));
                } else {
                    if (EPI == EPI_TANH_HILO) { d0 = tanhf(d0); d1 = tanhf(d1); }
                    __nv_bfloat16 h0 = __float2bfloat16(d0), h1 = __float2bfloat16(d1);
                    __nv_bfloat16 l0 = __float2bfloat16(d0 - __bfloat162float(h0));
                    __nv_bfloat16 l1 = __float2bfloat16(d1 - __bfloat162float(h1));
                    uint32_t ph = (uint32_t)__bfloat16_as_ushort(h0) |
                                  ((uint32_t)__bfloat16_as_ushort(h1) << 16);
                    uint32_t pl = (uint32_t)__bfloat16_as_ushort(l0) |
                                  ((uint32_t)__bfloat16_as_ushort(l1) << 16);
                    *(uint32_t*)(Dhi + rowoff + col) = ph;
                    *(uint32_t*)(Dlo + rowoff + col) = pl;
                    if (EPI == EPI_TANH_HILO)
                        *(float2*)(Dout + rowoff + col) = make_float2(d0, d1);
                }
            }
        }
    }
}

// ---------------- transpose + bf16 hi/lo split:  XT[c][r] = X[r][c] ----------------
__global__ void transconv_k(const float* __restrict__ X,
                            __nv_bfloat16* __restrict__ H, __nv_bfloat16* __restrict__ L,
                            int R, int C)
{
    __shared__ float tile[32][33];
    const int bz = blockIdx.z;
    const float* Xb = X + (size_t)bz * R * C;
    const int x0 = blockIdx.x * 32, y0 = blockIdx.y * 32;
    const int tx = threadIdx.x, ty = threadIdx.y;
#pragma unroll
    for (int j = 0; j < 4; j++)
        tile[ty + j * 8][tx] = Xb[(size_t)(y0 + ty + j * 8) * C + x0 + tx];
    __syncthreads();
    __nv_bfloat16* Hb = H + (size_t)bz * R * C;
    __nv_bfloat16* Lb = L + (size_t)bz * R * C;
#pragma unroll
    for (int j = 0; j < 4; j++) {
        float v = tile[tx][ty + j * 8];
        size_t o = (size_t)(x0 + ty + j * 8) * R + y0 + tx;
        __nv_bfloat16 h = __float2bfloat16(v);
        Hb[o] = h;
        Lb[o] = __float2bfloat16(v - __bfloat162float(h));
    }
}

__global__ void wconv_k(const float* __restrict__ X, __nv_bfloat16* __restrict__ H,
                        __nv_bfloat16* __restrict__ L, int n)
{
    int i = blockIdx.x * blockDim.x + threadIdx.x;
    if (i < n) {
        float v = X[i];
        __nv_bfloat16 h = __float2bfloat16(v);
        H[i] = h;
        L[i] = __float2bfloat16(v - __bfloat162float(h));
    }
}

// logits[b,t] = sum_f G[b,f,t]
__global__ void col_reduce_k(const float* __restrict__ G)
{
    int t = blockIdx.x * blockDim.x + threadIdx.x;
    int b = blockIdx.y;
    const float* g = G + (size_t)b * F_ * T_ + t;
    float acc = 0.0f;
#pragma unroll 8
    for (int f = 0; f < F_; f++) acc += g[(size_t)f * T_];
    g_logit[b * T_ + t] = acc;
}

__global__ void softmax_k(float* __restrict__ aq)
{
    __shared__ float sm[256];
    int b = blockIdx.x, tid = threadIdx.x;
    const float* lg = g_logit + b * T_;
    float v[4]; float vmax = -1e30f;
#pragma unroll
    for (int i = 0; i < 4; i++) { v[i] = lg[tid + i * 256]; vmax = fmaxf(vmax, v[i]); }
    sm[tid] = vmax; __syncthreads();
    for (int s = 128; s > 0; s >>= 1) { if (tid < s) sm[tid] = fmaxf(sm[tid], sm[tid + s]); __syncthreads(); }
    vmax = sm[0]; __syncthreads();
    float lsum = 0.0f;
#pragma unroll
    for (int i = 0; i < 4; i++) { v[i] = expf(v[i] - vmax); lsum += v[i]; }
    sm[tid] = lsum; __syncthreads();
    for (int s = 128; s > 0; s >>= 1) { if (tid < s) sm[tid] += sm[tid + s]; __syncthreads(); }
    float inv = 1.0f / sm[0];
#pragma unroll
    for (int i = 0; i < 4; i++) aq[b * T_ + tid + i * 256] = v[i] * inv;
}

__global__ void attn_k(const float* __restrict__ zr, const float* __restrict__ aq,
                       float* __restrict__ out)
{
    int gwarp = (blockIdx.x * blockDim.x + threadIdx.x) >> 5;
    int lane = threadIdx.x & 31;
    int b = gwarp >> 9, s = gwarp & (S_ - 1);
    const float* z = zr + ((size_t)b * S_ + s) * T_;
    const float* a = aq + b * T_;
    float acc = 0.0f;
#pragma unroll 4
    for (int t = lane; t < T_; t += 32) acc += z[t] * a[t];
#pragma unroll
    for (int o = 16; o > 0; o >>= 1) acc += __shfl_xor_sync(0xFFFFFFFFu, acc, o);
    if (lane == 0) out[b * S_ + s] = acc;
}

extern "C" void kernel_launch(void* const* d_in, const int* in_sizes, int n_in,
                              void* d_out, int out_size)
{
    const float* zr  = (const float*)d_in[0];
    const float* zh  = (const float*)d_in[1];
    const float* Wb  = (const float*)d_in[2];
    const float* Wq  = (const float*)d_in[3];
    const float* Wv  = (const float*)d_in[4];
    const float* whq = (const float*)d_in[5];

    float* out  = (float*)d_out;
    float* attn = out;
    float* aq   = out + B_ * S_;
    float* Cmat = out + B_ * S_ + B_ * T_;

    cudaFuncSetAttribute(mma_gemm<EPI_NONE>,      cudaFuncAttributeMaxDynamicSharedMemorySize, GEMM_SMEM);
    cudaFuncSetAttribute(mma_gemm<EPI_HILO>,      cudaFuncAttributeMaxDynamicSharedMemorySize, GEMM_SMEM);
    cudaFuncSetAttribute(mma_gemm<EPI_TANH_HILO>, cudaFuncAttributeMaxDynamicSharedMemorySize, GEMM_SMEM);
    cudaFuncSetAttribute(mma_gemm<EPI_WG>,        cudaFuncAttributeMaxDynamicSharedMemorySize, GEMM_SMEM);

    __nv_bfloat16 *zhT_hi, *zhT_lo, *zrT_hi, *zrT_lo, *auxT_hi, *auxT_lo;
    __nv_bfloat16 *C_hi, *C_lo, *a2_hi, *a2_lo;
    __nv_bfloat16 *Wb_hi, *Wb_lo, *Wq_hi, *Wq_lo, *Wv_hi, *Wv_lo;
    float *a3, *G;
    cudaGetSymbolAddress((void**)&zhT_hi, g_zhT_hi);   cudaGetSymbolAddress((void**)&zhT_lo, g_zhT_lo);
    cudaGetSymbolAddress((void**)&zrT_hi, g_zrT_hi);   cudaGetSymbolAddress((void**)&zrT_lo, g_zrT_lo);
    cudaGetSymbolAddress((void**)&auxT_hi, g_auxT_hi); cudaGetSymbolAddress((void**)&auxT_lo, g_auxT_lo);
    cudaGetSymbolAddress((void**)&C_hi, g_C_hi);       cudaGetSymbolAddress((void**)&C_lo, g_C_lo);
    cudaGetSymbolAddress((void**)&a2_hi, g_a2_hi);     cudaGetSymbolAddress((void**)&a2_lo, g_a2_lo);
    cudaGetSymbolAddress((void**)&Wb_hi, g_Wb_hi);     cudaGetSymbolAddress((void**)&Wb_lo, g_Wb_lo);
    cudaGetSymbolAddress((void**)&Wq_hi, g_Wq_hi);     cudaGetSymbolAddress((void**)&Wq_lo, g_Wq_lo);
    cudaGetSymbolAddress((void**)&Wv_hi, g_Wv_hi);     cudaGetSymbolAddress((void**)&Wv_lo, g_Wv_lo);
    cudaGetSymbolAddress((void**)&a3, g_a3);           cudaGetSymbolAddress((void**)&G, g_G);

    const long TS = (long)T_ * S_;
    const long TT = (long)T_ * T_;
    const long FT = (long)F_ * T_;

    // input conversions
    dim3 tb(32, 8);
    transconv_k<<<dim3(T_/32, S_/32, B_), tb>>>(zh, zhT_hi, zhT_lo, S_, T_);  // zhT[h][u]
    transconv_k<<<dim3(T_/32, S_/32, B_), tb>>>(zr, zrT_hi, zrT_lo, S_, T_);  // zrT[t][s]
    wconv_k<<<(S_*S_)/256, 256>>>(Wb, Wb_hi, Wb_lo, S_*S_);
    wconv_k<<<(F_*S_)/256, 256>>>(Wq, Wq_hi, Wq_lo, F_*S_);
    wconv_k<<<(F_*S_)/256, 256>>>(Wv, Wv_hi, Wv_lo, F_*S_);

    // G1: auxT[h][s] = sum_u zhT[h][u] * Wb[s][u]         M=T, N=S, K=S
    mma_gemm<EPI_HILO><<<dim3(S_/BN, T_/BM, B_), 256, GEMM_SMEM>>>(
        zhT_hi, zhT_lo, Wb_hi, Wb_lo, nullptr, auxT_hi, auxT_lo, nullptr, nullptr,
        T_, S_, S_, TS, 0L, TS, 0L);

    // G2: C[t][h] = tanh( sum_s zrT[t][s] * auxT[h][s] )  M=T, N=T, K=S
    mma_gemm<EPI_TANH_HILO><<<dim3(T_/BN, T_/BM, B_), 256, GEMM_SMEM>>>(
        zrT_hi, zrT_lo, auxT_hi, auxT_lo, Cmat, C_hi, C_lo, nullptr, nullptr,
        T_, T_, S_, TS, TS, TT, 0L);

    // G3: aux2[f][h] = sum_s Wv[f][s] * zhT[h][s]         M=F, N=T, K=S
    mma_gemm<EPI_HILO><<<dim3(T_/BN, F_/BM, B_), 256, GEMM_SMEM>>>(
        Wv_hi, Wv_lo, zhT_hi, zhT_lo, nullptr, a2_hi, a2_lo, nullptr, nullptr,
        F_, T_, S_, 0L, TS, FT, 0L);

    // G4: aux3[f][t] = sum_s Wq[f][s] * zrT[t][s]         M=F, N=T, K=S
    mma_gemm<EPI_NONE><<<dim3(T_/BN, F_/BM, B_), 256, GEMM_SMEM>>>(
        Wq_hi, Wq_lo, zrT_hi, zrT_lo, a3, nullptr, nullptr, nullptr, nullptr,
        F_, T_, S_, 0L, TS, FT, 0L);

    // G5: G[f][t] = w_hq[f] * tanh( aux3 + sum_h aux2[f][h]*C[t][h] )  M=F, N=T, K=T
    mma_gemm<EPI_WG><<<dim3(T_/BN, F_/BM, B_), 256, GEMM_SMEM>>>(
        a2_hi, a2_lo, C_hi, C_lo, G, nullptr, nullptr, a3, whq,
        F_, T_, T_, FT, TT, FT, FT);

    col_reduce_k<<<dim3(T_/256, B_), 256>>>(G);
    softmax_k<<<B_, 256>>>(aq);
    attn_k<<<(B_ * S_ * 32) / 256, 256>>>(zr, aq, attn);
}

// round 4
// speedup vs baseline: 2.2778x; 1.4828x over previous
#include <cuda_runtime.h>
#include <cuda_bf16.h>
#include <cstdint>
#include <math.h>

#define B_ 32
#define S_ 512
#define F_ 512
#define T_ 1024

#define BM 128
#define BN 128
#define BK 32
// per tile: 128 rows x (32+8) bf16 = 80B stride, 10240B
#define TILE_B   10240
#define STAGE_B  (4 * TILE_B)
#define NSTAGE   3
#define GEMM_SMEM (NSTAGE * STAGE_B)
#define LDS_ROW  80

// ---------------- scratch (allocation-free) ----------------
__device__ __nv_bfloat16 g_zhT_hi[(size_t)B_*T_*S_];
__device__ __nv_bfloat16 g_zhT_lo[(size_t)B_*T_*S_];
__device__ __nv_bfloat16 g_zrT_hi[(size_t)B_*T_*S_];
__device__ __nv_bfloat16 g_zrT_lo[(size_t)B_*T_*S_];
__device__ __nv_bfloat16 g_auxT_hi[(size_t)B_*T_*S_];
__device__ __nv_bfloat16 g_auxT_lo[(size_t)B_*T_*S_];
__device__ __nv_bfloat16 g_C_hi[(size_t)B_*T_*T_];
__device__ __nv_bfloat16 g_C_lo[(size_t)B_*T_*T_];
__device__ __nv_bfloat16 g_a2_hi[(size_t)B_*F_*T_];
__device__ __nv_bfloat16 g_a2_lo[(size_t)B_*F_*T_];
__device__ float g_a3[(size_t)B_*F_*T_];
__device__ float g_G [(size_t)B_*F_*T_];
__device__ __nv_bfloat16 g_Wb_hi[S_*S_], g_Wb_lo[S_*S_];
__device__ __nv_bfloat16 g_Wq_hi[F_*S_], g_Wq_lo[F_*S_];
__device__ __nv_bfloat16 g_Wv_hi[F_*S_], g_Wv_lo[F_*S_];
__device__ float g_logit[B_*T_];

// ---------------- helpers ----------------
static __device__ __forceinline__ uint32_t s2u(const void* p){
    uint32_t a;
    asm("{ .reg .u64 t; cvta.to.shared.u64 t, %1; cvt.u32.u64 %0, t; }" : "=r"(a) : "l"(p));
    return a;
}
static __device__ __forceinline__ void cp16(uint32_t dst, const void* src){
    asm volatile("cp.async.cg.shared.global [%0], [%1], 16;" :: "r"(dst), "l"(src) : "memory");
}
static __device__ __forceinline__ void cp_commit(){
    asm volatile("cp.async.commit_group;" ::: "memory");
}
static __device__ __forceinline__ void ldm_x4(uint32_t& r0, uint32_t& r1, uint32_t& r2, uint32_t& r3, uint32_t a){
    asm volatile("ldmatrix.sync.aligned.m8n8.x4.shared.b16 {%0,%1,%2,%3}, [%4];"
                 : "=r"(r0), "=r"(r1), "=r"(r2), "=r"(r3) : "r"(a));
}
static __device__ __forceinline__ void mma16816(float* d, const uint32_t* a, const uint32_t* b){
    asm volatile("mma.sync.aligned.m16n8k16.row.col.f32.bf16.bf16.f32 "
                 "{%0,%1,%2,%3}, {%4,%5,%6,%7}, {%8,%9}, {%0,%1,%2,%3};"
                 : "+f"(d[0]), "+f"(d[1]), "+f"(d[2]), "+f"(d[3])
                 : "r"(a[0]), "r"(a[1]), "r"(a[2]), "r"(a[3]), "r"(b[0]), "r"(b[1]));
}

enum { EPI_NONE = 0, EPI_HILO = 1, EPI_TANH_HILO = 2, EPI_WG = 3 };

// ---------------------------------------------------------------------------
// bf16 mma.sync GEMM, 3-term hi/lo compensation, 3-stage cp.async pipeline.
// D[b][m][n] = epi( sum_k (Ahi+Alo)[m][k]*(Bhi+Blo)[n][k] )   (lo*lo dropped)
// A,B row-major, K contiguous (row stride = K). Output row-major, ld = N.
// ---------------------------------------------------------------------------
template <int EPI>
__global__ __launch_bounds__(256)
void mma_gemm(const __nv_bfloat16* __restrict__ Ahi, const __nv_bfloat16* __restrict__ Alo,
              const __nv_bfloat16* __restrict__ Bhi, const __nv_bfloat16* __restrict__ Blo,
              float* __restrict__ Dout,
              __nv_bfloat16* __restrict__ Dhi, __nv_bfloat16* __restrict__ Dlo,
              const float* __restrict__ Eadd, const float* __restrict__ wv,
              int M, int N, int K, long sA, long sB, long sD, long sE)
{
    extern __shared__ char smem[];
    const uint32_t sb = s2u(smem);
    const int tid = threadIdx.x;
    const int wid = tid >> 5, lane = tid & 31;
    const int b = blockIdx.z;
    const int m0 = blockIdx.y * BM, n0 = blockIdx.x * BN;

    const __nv_bfloat16* srcA_hi = Ahi + (size_t)b * sA;
    const __nv_bfloat16* srcA_lo = Alo + (size_t)b * sA;
    const __nv_bfloat16* srcB_hi = Bhi + (size_t)b * sB;
    const __nv_bfloat16* srcB_lo = Blo + (size_t)b * sB;

    // loader geometry: 2048 16B units per stage (4 tiles x 512), 8 per thread
    const __nv_bfloat16* gsrc[8];
    uint32_t sdst[8];
#pragma unroll
    for (int u = 0; u < 8; u++) {
        int unit = tid + u * 256;
        int t = unit >> 9;
        int r = (unit >> 2) & 127;
        int c = unit & 3;
        const __nv_bfloat16* base =
            (t == 0) ? srcA_hi : (t == 1) ? srcA_lo : (t == 2) ? srcB_hi : srcB_lo;
        int row0 = (t < 2) ? m0 : n0;
        gsrc[u] = base + (size_t)(row0 + r) * K + c * 8;
        sdst[u] = sb + t * TILE_B + r * LDS_ROW + c * 16;
    }

    float acc[4][4][4];
#pragma unroll
    for (int i = 0; i < 4; i++)
#pragma unroll
        for (int j = 0; j < 4; j++)
#pragma unroll
            for (int q = 0; q < 4; q++) acc[i][j][q] = 0.0f;

    const int wm = (wid >> 2) * 64;
    const int wn = (wid & 3) * 32;

    uint32_t a_addr[4];
#pragma unroll
    for (int mf = 0; mf < 4; mf++) {
        int row = wm + mf * 16 + (lane & 15);
        int colb = (lane >> 4) * 16;
        a_addr[mf] = sb + row * LDS_ROW + colb;
    }
    uint32_t b_addr[2];
#pragma unroll
    for (int nt = 0; nt < 2; nt++) {
        int row = wn + nt * 16 + (lane & 7) + ((lane & 16) >> 1);
        int colb = ((lane >> 3) & 1) * 16;
        b_addr[nt] = sb + row * LDS_ROW + colb;
    }

    const int NC = K / BK;   // >= 16 for all our shapes

    // prologue: stages 0, 1
#pragma unroll
    for (int u = 0; u < 8; u++) cp16(sdst[u], gsrc[u]);
    cp_commit();
#pragma unroll
    for (int u = 0; u < 8; u++) cp16(sdst[u] + STAGE_B, gsrc[u] + BK);
    cp_commit();

    // fragment double buffers
    uint32_t ah[2][4], al[2][4], bh[2][4][2], bl[2][4][2];

    auto load_frags = [&](int slot, uint32_t base) {
#pragma unroll
        for (int nt = 0; nt < 2; nt++) {
            ldm_x4(bh[slot][nt*2][0], bh[slot][nt*2][1], bh[slot][nt*2+1][0], bh[slot][nt*2+1][1],
                   b_addr[nt] + 2 * TILE_B + base);
            ldm_x4(bl[slot][nt*2][0], bl[slot][nt*2][1], bl[slot][nt*2+1][0], bl[slot][nt*2+1][1],
                   b_addr[nt] + 3 * TILE_B + base);
        }
        // A loads folded into the mf loop of the consumer for slot reuse; here load all:
    };

    for (int i = 0; i < NC; i++) {
        // wait for stage i (newest outstanding group is i+1)
        if (i + 1 < NC) asm volatile("cp.async.wait_group 1;" ::: "memory");
        else            asm volatile("cp.async.wait_group 0;" ::: "memory");
        __syncthreads();

        const uint32_t stg = (uint32_t)(i % NSTAGE) * STAGE_B;

        // preload k-step 0 fragments (B all, A all)
        load_frags(0, stg);
#pragma unroll
        for (int mf = 0; mf < 4; mf++) {
            ldm_x4(ah[0][0], ah[0][1], ah[0][2], ah[0][3], a_addr[mf] + stg);
            ldm_x4(al[0][0], al[0][1], al[0][2], al[0][3], a_addr[mf] + TILE_B + stg);
            // stash per-mf A frags in slot arrays below instead
            break;
        }

        // We keep A fragments per-mf (loaded inside the mf loop) and
        // double-buffer only across k-steps for B; A ldmatrix for mf+1 is
        // issued before the MMA block of mf to overlap LDS latency.
#pragma unroll
        for (int ks = 0; ks < 2; ks++) {
            const uint32_t kb = stg + ks * 32;
            if (ks == 1) load_frags(1, kb);
            uint32_t (*bhc)[2] = bh[ks], (*blc)[2] = bl[ks];

            uint32_t ahc[4], alc[4], ahn[4], aln[4];
            ldm_x4(ahc[0], ahc[1], ahc[2], ahc[3], a_addr[0] + kb);
            ldm_x4(alc[0], alc[1], alc[2], alc[3], a_addr[0] + TILE_B + kb);
#pragma unroll
            for (int mf = 0; mf < 4; mf++) {
                if (mf + 1 < 4) {
                    ldm_x4(ahn[0], ahn[1], ahn[2], ahn[3], a_addr[mf+1] + kb);
                    ldm_x4(aln[0], aln[1], aln[2], aln[3], a_addr[mf+1] + TILE_B + kb);
                }
#pragma unroll
                for (int nf = 0; nf < 4; nf++) {
                    mma16816(acc[mf][nf], ahc, bhc[nf]);
                    mma16816(acc[mf][nf], ahc, blc[nf]);
                    mma16816(acc[mf][nf], alc, bhc[nf]);
                }
#pragma unroll
                for (int q = 0; q < 4; q++) { ahc[q] = ahn[q]; alc[q] = aln[q]; }
            }
        }
        __syncthreads();

        // issue load for stage i+2 into buffer (i+2)%NSTAGE (freed: stage i-1)
        if (i + 2 < NC) {
            const uint32_t dst = (uint32_t)((i + 2) % NSTAGE) * STAGE_B;
            const int koff = (i + 2) * BK;
#pragma unroll
            for (int u = 0; u < 8; u++) cp16(sdst[u] + dst, gsrc[u] + koff);
            cp_commit();
        }
    }

    // ---- epilogue ----
    const int g = lane >> 2, tg = lane & 3;
#pragma unroll
    for (int mf = 0; mf < 4; mf++) {
#pragma unroll
        for (int h = 0; h < 2; h++) {
            const int row = m0 + wm + mf * 16 + g + h * 8;
            float w = 0.0f;
            if (EPI == EPI_WG) w = wv[row];
            const size_t rowoff = (size_t)b * sD + (size_t)row * N;
#pragma unroll
            for (int nf = 0; nf < 4; nf++) {
                const int col = n0 + wn + nf * 8 + tg * 2;
                float d0 = acc[mf][nf][h * 2 + 0];
                float d1 = acc[mf][nf][h * 2 + 1];
                if (EPI == EPI_NONE) {
                    *(float2*)(Dout + rowoff + col) = make_float2(d0, d1);
                } else if (EPI == EPI_WG) {
                    const float2 e = *(const float2*)(Eadd + (size_t)b * sE + (size_t)row * N + col);
                    *(float2*)(Dout + rowoff + col) =
                        make_float2(w * tanhf(d0 + e.x), w * tanhf(d1 + e.y));
                } else {
                    if (EPI == EPI_TANH_HILO) { d0 = tanhf(d0); d1 = tanhf(d1); }
                    __nv_bfloat16 h0 = __float2bfloat16(d0), h1 = __float2bfloat16(d1);
                    __nv_bfloat16 l0 = __float2bfloat16(d0 - __bfloat162float(h0));
                    __nv_bfloat16 l1 = __float2bfloat16(d1 - __bfloat162float(h1));
                    uint32_t ph = (uint32_t)__bfloat16_as_ushort(h0) |
                                  ((uint32_t)__bfloat16_as_ushort(h1) << 16);
                    uint32_t pl = (uint32_t)__bfloat16_as_ushort(l0) |
                                  ((uint32_t)__bfloat16_as_ushort(l1) << 16);
                    *(uint32_t*)(Dhi + rowoff + col) = ph;
                    *(uint32_t*)(Dlo + rowoff + col) = pl;
                    if (EPI == EPI_TANH_HILO)
                        *(float2*)(Dout + rowoff + col) = make_float2(d0, d1);
                }
            }
        }
    }
}

// ---------------- transpose + bf16 hi/lo split ----------------
__global__ void transconv_k(const float* __restrict__ X,
                            __nv_bfloat16* __restrict__ H, __nv_bfloat16* __restrict__ L,
                            int R, int C)
{
    __shared__ float tile[32][33];
    const int bz = blockIdx.z;
    const float* Xb = X + (size_t)bz * R * C;
    const int x0 = blockIdx.x * 32, y0 = blockIdx.y * 32;
    const int tx = threadIdx.x, ty = threadIdx.y;
#pragma unroll
    for (int j = 0; j < 4; j++)
        tile[ty + j * 8][tx] = Xb[(size_t)(y0 + ty + j * 8) * C + x0 + tx];
    __syncthreads();
    __nv_bfloat16* Hb = H + (size_t)bz * R * C;
    __nv_bfloat16* Lb = L + (size_t)bz * R * C;
#pragma unroll
    for (int j = 0; j < 4; j++) {
        float v = tile[tx][ty + j * 8];
        size_t o = (size_t)(x0 + ty + j * 8) * R + y0 + tx;
        __nv_bfloat16 h = __float2bfloat16(v);
        Hb[o] = h;
        Lb[o] = __float2bfloat16(v - __bfloat162float(h));
    }
}

// all three weight splits in a single launch (keeps GEMMs early for ncu)
__global__ void wconv_all_k(const float* __restrict__ Wb, const float* __restrict__ Wq,
                            const float* __restrict__ Wv)
{
    int i = blockIdx.x * blockDim.x + threadIdx.x;
    int which = blockIdx.y;
    const float* X = (which == 0) ? Wb : (which == 1) ? Wq : Wv;
    __nv_bfloat16* H = (which == 0) ? g_Wb_hi : (which == 1) ? g_Wq_hi : g_Wv_hi;
    __nv_bfloat16* L = (which == 0) ? g_Wb_lo : (which == 1) ? g_Wq_lo : g_Wv_lo;
    float v = X[i];
    __nv_bfloat16 h = __float2bfloat16(v);
    H[i] = h;
    L[i] = __float2bfloat16(v - __bfloat162float(h));
}

__global__ void col_reduce_k(const float* __restrict__ G)
{
    int t = blockIdx.x * blockDim.x + threadIdx.x;
    int b = blockIdx.y;
    const float* g = G + (size_t)b * F_ * T_ + t;
    float acc = 0.0f;
#pragma unroll 8
    for (int f = 0; f < F_; f++) acc += g[(size_t)f * T_];
    g_logit[b * T_ + t] = acc;
}

__global__ void softmax_k(float* __restrict__ aq)
{
    __shared__ float sm[256];
    int b = blockIdx.x, tid = threadIdx.x;
    const float* lg = g_logit + b * T_;
    float v[4]; float vmax = -1e30f;
#pragma unroll
    for (int i = 0; i < 4; i++) { v[i] = lg[tid + i * 256]; vmax = fmaxf(vmax, v[i]); }
    sm[tid] = vmax; __syncthreads();
    for (int s = 128; s > 0; s >>= 1) { if (tid < s) sm[tid] = fmaxf(sm[tid], sm[tid + s]); __syncthreads(); }
    vmax = sm[0]; __syncthreads();
    float lsum = 0.0f;
#pragma unroll
    for (int i = 0; i < 4; i++) { v[i] = expf(v[i] - vmax); lsum += v[i]; }
    sm[tid] = lsum; __syncthreads();
    for (int s = 128; s > 0; s >>= 1) { if (tid < s) sm[tid] += sm[tid + s]; __syncthreads(); }
    float inv = 1.0f / sm[0];
#pragma unroll
    for (int i = 0; i < 4; i++) aq[b * T_ + tid + i * 256] = v[i] * inv;
}

__global__ void attn_k(const float* __restrict__ zr, const float* __restrict__ aq,
                       float* __restrict__ out)
{
    int gwarp = (blockIdx.x * blockDim.x + threadIdx.x) >> 5;
    int lane = threadIdx.x & 31;
    int b = gwarp >> 9, s = gwarp & (S_ - 1);
    const float* z = zr + ((size_t)b * S_ + s) * T_;
    const float* a = aq + b * T_;
    float acc = 0.0f;
#pragma unroll 4
    for (int t = lane; t < T_; t += 32) acc += z[t] * a[t];
#pragma unroll
    for (int o = 16; o > 0; o >>= 1) acc += __shfl_xor_sync(0xFFFFFFFFu, acc, o);
    if (lane == 0) out[b * S_ + s] = acc;
}

extern "C" void kernel_launch(void* const* d_in, const int* in_sizes, int n_in,
                              void* d_out, int out_size)
{
    const float* zr  = (const float*)d_in[0];
    const float* zh  = (const float*)d_in[1];
    const float* Wb  = (const float*)d_in[2];
    const float* Wq  = (const float*)d_in[3];
    const float* Wv  = (const float*)d_in[4];
    const float* whq = (const float*)d_in[5];

    float* out  = (float*)d_out;
    float* attn = out;
    float* aq   = out + B_ * S_;
    float* Cmat = out + B_ * S_ + B_ * T_;

    cudaFuncSetAttribute(mma_gemm<EPI_NONE>,      cudaFuncAttributeMaxDynamicSharedMemorySize, GEMM_SMEM);
    cudaFuncSetAttribute(mma_gemm<EPI_HILO>,      cudaFuncAttributeMaxDynamicSharedMemorySize, GEMM_SMEM);
    cudaFuncSetAttribute(mma_gemm<EPI_TANH_HILO>, cudaFuncAttributeMaxDynamicSharedMemorySize, GEMM_SMEM);
    cudaFuncSetAttribute(mma_gemm<EPI_WG>,        cudaFuncAttributeMaxDynamicSharedMemorySize, GEMM_SMEM);

    __nv_bfloat16 *zhT_hi, *zhT_lo, *zrT_hi, *zrT_lo, *auxT_hi, *auxT_lo;
    __nv_bfloat16 *C_hi, *C_lo, *a2_hi, *a2_lo;
    __nv_bfloat16 *Wb_hi, *Wb_lo, *Wq_hi, *Wq_lo, *Wv_hi, *Wv_lo;
    float *a3, *G;
    cudaGetSymbolAddress((void**)&zhT_hi, g_zhT_hi);   cudaGetSymbolAddress((void**)&zhT_lo, g_zhT_lo);
    cudaGetSymbolAddress((void**)&zrT_hi, g_zrT_hi);   cudaGetSymbolAddress((void**)&zrT_lo, g_zrT_lo);
    cudaGetSymbolAddress((void**)&auxT_hi, g_auxT_hi); cudaGetSymbolAddress((void**)&auxT_lo, g_auxT_lo);
    cudaGetSymbolAddress((void**)&C_hi, g_C_hi);       cudaGetSymbolAddress((void**)&C_lo, g_C_lo);
    cudaGetSymbolAddress((void**)&a2_hi, g_a2_hi);     cudaGetSymbolAddress((void**)&a2_lo, g_a2_lo);
    cudaGetSymbolAddress((void**)&Wb_hi, g_Wb_hi);     cudaGetSymbolAddress((void**)&Wb_lo, g_Wb_lo);
    cudaGetSymbolAddress((void**)&Wq_hi, g_Wq_hi);     cudaGetSymbolAddress((void**)&Wq_lo, g_Wq_lo);
    cudaGetSymbolAddress((void**)&Wv_hi, g_Wv_hi);     cudaGetSymbolAddress((void**)&Wv_lo, g_Wv_lo);
    cudaGetSymbolAddress((void**)&a3, g_a3);           cudaGetSymbolAddress((void**)&G, g_G);

    const long TS = (long)T_ * S_;
    const long TT = (long)T_ * T_;
    const long FT = (long)F_ * T_;

    // conversions (3 launches total so GEMMs land in ncu's capture window)
    wconv_all_k<<<dim3((F_*S_)/256, 3), 256>>>(Wb, Wq, Wv);
    dim3 tb(32, 8);
    transconv_k<<<dim3(T_/32, S_/32, B_), tb>>>(zh, zhT_hi, zhT_lo, S_, T_);
    transconv_k<<<dim3(T_/32, S_/32, B_), tb>>>(zr, zrT_hi, zrT_lo, S_, T_);

    // G1: auxT[h][s] = sum_u zhT[h][u] * Wb[s][u]         M=T, N=S, K=S
    mma_gemm<EPI_HILO><<<dim3(S_/BN, T_/BM, B_), 256, GEMM_SMEM>>>(
        zhT_hi, zhT_lo, Wb_hi, Wb_lo, nullptr, auxT_hi, auxT_lo, nullptr, nullptr,
        T_, S_, S_, TS, 0L, TS, 0L);

    // G2: C[t][h] = tanh( sum_s zrT[t][s] * auxT[h][s] )  M=T, N=T, K=S
    mma_gemm<EPI_TANH_HILO><<<dim3(T_/BN, T_/BM, B_), 256, GEMM_SMEM>>>(
        zrT_hi, zrT_lo, auxT_hi, auxT_lo, Cmat, C_hi, C_lo, nullptr, nullptr,
        T_, T_, S_, TS, TS, TT, 0L);

    // G3: aux2[f][h] = sum_s Wv[f][s] * zhT[h][s]         M=F, N=T, K=S
    mma_gemm<EPI_HILO><<<dim3(T_/BN, F_/BM, B_), 256, GEMM_SMEM>>>(
        Wv_hi, Wv_lo, zhT_hi, zhT_lo, nullptr, a2_hi, a2_lo, nullptr, nullptr,
        F_, T_, S_, 0L, TS, FT, 0L);

    // G4: aux3[f][t] = sum_s Wq[f][s] * zrT[t][s]         M=F, N=T, K=S
    mma_gemm<EPI_NONE><<<dim3(T_/BN, F_/BM, B_), 256, GEMM_SMEM>>>(
        Wq_hi, Wq_lo, zrT_hi, zrT_lo, a3, nullptr, nullptr, nullptr, nullptr,
        F_, T_, S_, 0L, TS, FT, 0L);

    // G5: G[f][t] = w_hq[f] * tanh( aux3 + sum_h aux2[f][h]*C[t][h] )  M=F, N=T, K=T
    mma_gemm<EPI_WG><<<dim3(T_/BN, F_/BM, B_), 256, GEMM_SMEM>>>(
        a2_hi, a2_lo, C_hi, C_lo, G, nullptr, nullptr, a3, whq,
        F_, T_, T_, FT, TT, FT, FT);

    col_reduce_k<<<dim3(T_/256, B_), 256>>>(G);
    softmax_k<<<B_, 256>>>(aq);
    attn_k<<<(B_ * S_ * 32) / 256, 256>>>(zr, aq, attn);
}

// round 5
// speedup vs baseline: 2.7525x; 1.2084x over previous
#include <cuda_runtime.h>
#include <cuda_bf16.h>
#include <cstdint>
#include <math.h>

#define B_ 32
#define S_ 512
#define F_ 512
#define T_ 1024

#define BM 128
#define BN 128
#define BK 32
// per tile: 128 rows x (32+8) bf16 = 80B stride, 10240B
#define TILE_B   10240
#define STAGE_B  (4 * TILE_B)
#define NSTAGE   2
#define GEMM_SMEM (NSTAGE * STAGE_B)    // 80 KB -> 2 CTAs/SM
#define LDS_ROW  80

// ---------------- scratch (allocation-free) ----------------
__device__ __nv_bfloat16 g_zhT_hi[(size_t)B_*T_*S_];
__device__ __nv_bfloat16 g_zhT_lo[(size_t)B_*T_*S_];
__device__ __nv_bfloat16 g_zrT_hi[(size_t)B_*T_*S_];
__device__ __nv_bfloat16 g_zrT_lo[(size_t)B_*T_*S_];
__device__ __nv_bfloat16 g_auxT_hi[(size_t)B_*T_*S_];
__device__ __nv_bfloat16 g_auxT_lo[(size_t)B_*T_*S_];
__device__ __nv_bfloat16 g_C_hi[(size_t)B_*T_*T_];
__device__ __nv_bfloat16 g_C_lo[(size_t)B_*T_*T_];
__device__ __nv_bfloat16 g_a2_hi[(size_t)B_*F_*T_];
__device__ __nv_bfloat16 g_a2_lo[(size_t)B_*F_*T_];
__device__ float g_a3[(size_t)B_*F_*T_];
__device__ float g_G [(size_t)B_*F_*T_];
__device__ __nv_bfloat16 g_Wb_hi[S_*S_], g_Wb_lo[S_*S_];
__device__ __nv_bfloat16 g_Wq_hi[F_*S_], g_Wq_lo[F_*S_];
__device__ __nv_bfloat16 g_Wv_hi[F_*S_], g_Wv_lo[F_*S_];
__device__ float g_logit[B_*T_];

// ---------------- helpers ----------------
static __device__ __forceinline__ uint32_t s2u(const void* p){
    uint32_t a;
    asm("{ .reg .u64 t; cvta.to.shared.u64 t, %1; cvt.u32.u64 %0, t; }" : "=r"(a) : "l"(p));
    return a;
}
static __device__ __forceinline__ void cp16(uint32_t dst, const void* src){
    asm volatile("cp.async.cg.shared.global [%0], [%1], 16;" :: "r"(dst), "l"(src) : "memory");
}
static __device__ __forceinline__ void cp_commit(){
    asm volatile("cp.async.commit_group;" ::: "memory");
}
static __device__ __forceinline__ void ldm_x4(uint32_t& r0, uint32_t& r1, uint32_t& r2, uint32_t& r3, uint32_t a){
    asm volatile("ldmatrix.sync.aligned.m8n8.x4.shared.b16 {%0,%1,%2,%3}, [%4];"
                 : "=r"(r0), "=r"(r1), "=r"(r2), "=r"(r3) : "r"(a));
}
static __device__ __forceinline__ void mma16816(float* d, const uint32_t* a, const uint32_t* b){
    asm volatile("mma.sync.aligned.m16n8k16.row.col.f32.bf16.bf16.f32 "
                 "{%0,%1,%2,%3}, {%4,%5,%6,%7}, {%8,%9}, {%0,%1,%2,%3};"
                 : "+f"(d[0]), "+f"(d[1]), "+f"(d[2]), "+f"(d[3])
                 : "r"(a[0]), "r"(a[1]), "r"(a[2]), "r"(a[3]), "r"(b[0]), "r"(b[1]));
}

enum { EPI_NONE = 0, EPI_HILO = 1, EPI_TANH_HILO = 2, EPI_WG = 3 };

// ---------------------------------------------------------------------------
// bf16 mma.sync GEMM, 3-term hi/lo compensation, 2-stage cp.async pipeline,
// 2 CTAs/SM. MMA issue order is pass-major (same-accumulator reuse distance 4)
// to avoid HMMA RAW stalls.
// ---------------------------------------------------------------------------
template <int EPI>
__global__ __launch_bounds__(256, 2)
void mma_gemm(const __nv_bfloat16* __restrict__ Ahi, const __nv_bfloat16* __restrict__ Alo,
              const __nv_bfloat16* __restrict__ Bhi, const __nv_bfloat16* __restrict__ Blo,
              float* __restrict__ Dout,
              __nv_bfloat16* __restrict__ Dhi, __nv_bfloat16* __restrict__ Dlo,
              const float* __restrict__ Eadd, const float* __restrict__ wv,
              int M, int N, int K, long sA, long sB, long sD, long sE)
{
    extern __shared__ char smem[];
    const uint32_t sb = s2u(smem);
    const int tid = threadIdx.x;
    const int wid = tid >> 5, lane = tid & 31;
    const int b = blockIdx.z;
    const int m0 = blockIdx.y * BM, n0 = blockIdx.x * BN;

    const __nv_bfloat16* srcA_hi = Ahi + (size_t)b * sA;
    const __nv_bfloat16* srcA_lo = Alo + (size_t)b * sA;
    const __nv_bfloat16* srcB_hi = Bhi + (size_t)b * sB;
    const __nv_bfloat16* srcB_lo = Blo + (size_t)b * sB;

    // loader geometry: 2048 16B units per stage (4 tiles x 512), 8 per thread
    const __nv_bfloat16* gsrc[8];
    uint32_t sdst[8];
#pragma unroll
    for (int u = 0; u < 8; u++) {
        int unit = tid + u * 256;
        int t = unit >> 9;
        int r = (unit >> 2) & 127;
        int c = unit & 3;
        const __nv_bfloat16* base =
            (t == 0) ? srcA_hi : (t == 1) ? srcA_lo : (t == 2) ? srcB_hi : srcB_lo;
        int row0 = (t < 2) ? m0 : n0;
        gsrc[u] = base + (size_t)(row0 + r) * K + c * 8;
        sdst[u] = sb + t * TILE_B + r * LDS_ROW + c * 16;
    }

    float acc[4][4][4];
#pragma unroll
    for (int i = 0; i < 4; i++)
#pragma unroll
        for (int j = 0; j < 4; j++)
#pragma unroll
            for (int q = 0; q < 4; q++) acc[i][j][q] = 0.0f;

    const int wm = (wid >> 2) * 64;
    const int wn = (wid & 3) * 32;

    uint32_t a_addr[4];
#pragma unroll
    for (int mf = 0; mf < 4; mf++) {
        int row = wm + mf * 16 + (lane & 15);
        int colb = (lane >> 4) * 16;
        a_addr[mf] = sb + row * LDS_ROW + colb;
    }
    uint32_t b_addr[2];
#pragma unroll
    for (int nt = 0; nt < 2; nt++) {
        int row = wn + nt * 16 + (lane & 7) + ((lane & 16) >> 1);
        int colb = ((lane >> 3) & 1) * 16;
        b_addr[nt] = sb + row * LDS_ROW + colb;
    }

    const int NC = K / BK;

    // prologue: stages 0, 1
#pragma unroll
    for (int u = 0; u < 8; u++) cp16(sdst[u], gsrc[u]);
    cp_commit();
#pragma unroll
    for (int u = 0; u < 8; u++) cp16(sdst[u] + STAGE_B, gsrc[u] + BK);
    cp_commit();

    for (int i = 0; i < NC; i++) {
        if (i + 1 < NC) asm volatile("cp.async.wait_group 1;" ::: "memory");
        else            asm volatile("cp.async.wait_group 0;" ::: "memory");
        __syncthreads();

        const uint32_t stg = (uint32_t)(i & 1) * STAGE_B;

#pragma unroll
        for (int ks = 0; ks < 2; ks++) {
            const uint32_t kb = stg + ks * 32;

            // B fragments: hi & lo, all 4 n-tiles
            uint32_t bh[4][2], bl[4][2];
#pragma unroll
            for (int nt = 0; nt < 2; nt++) {
                ldm_x4(bh[nt*2][0], bh[nt*2][1], bh[nt*2+1][0], bh[nt*2+1][1],
                       b_addr[nt] + 2 * TILE_B + kb);
                ldm_x4(bl[nt*2][0], bl[nt*2][1], bl[nt*2+1][0], bl[nt*2+1][1],
                       b_addr[nt] + 3 * TILE_B + kb);
            }

            uint32_t ah[4], ahn[4], al[4];
            ldm_x4(ah[0], ah[1], ah[2], ah[3], a_addr[0] + kb);
#pragma unroll
            for (int mf = 0; mf < 4; mf++) {
                if (mf + 1 < 4)
                    ldm_x4(ahn[0], ahn[1], ahn[2], ahn[3], a_addr[mf+1] + kb);
                // pass 0: Ah*Bh   (accumulator reuse distance = 4 MMAs)
#pragma unroll
                for (int nf = 0; nf < 4; nf++) mma16816(acc[mf][nf], ah, bh[nf]);
                // load A-lo while pass-1 MMAs run
                ldm_x4(al[0], al[1], al[2], al[3], a_addr[mf] + TILE_B + kb);
                // pass 1: Ah*Bl
#pragma unroll
                for (int nf = 0; nf < 4; nf++) mma16816(acc[mf][nf], ah, bl[nf]);
                // pass 2: Al*Bh
#pragma unroll
                for (int nf = 0; nf < 4; nf++) mma16816(acc[mf][nf], al, bh[nf]);
#pragma unroll
                for (int q = 0; q < 4; q++) ah[q] = ahn[q];
            }
        }
        __syncthreads();

        // issue load for stage i+2 into buffer (i+2)&1 (just freed)
        if (i + 2 < NC) {
            const uint32_t dst = (uint32_t)((i + 2) & 1) * STAGE_B;
            const int koff = (i + 2) * BK;
#pragma unroll
            for (int u = 0; u < 8; u++) cp16(sdst[u] + dst, gsrc[u] + koff);
            cp_commit();
        }
    }

    // ---- epilogue ----
    const int g = lane >> 2, tg = lane & 3;
#pragma unroll
    for (int mf = 0; mf < 4; mf++) {
#pragma unroll
        for (int h = 0; h < 2; h++) {
            const int row = m0 + wm + mf * 16 + g + h * 8;
            float w = 0.0f;
            if (EPI == EPI_WG) w = wv[row];
            const size_t rowoff = (size_t)b * sD + (size_t)row * N;
#pragma unroll
            for (int nf = 0; nf < 4; nf++) {
                const int col = n0 + wn + nf * 8 + tg * 2;
                float d0 = acc[mf][nf][h * 2 + 0];
                float d1 = acc[mf][nf][h * 2 + 1];
                if (EPI == EPI_NONE) {
                    *(float2*)(Dout + rowoff + col) = make_float2(d0, d1);
                } else if (EPI == EPI_WG) {
                    const float2 e = *(const float2*)(Eadd + (size_t)b * sE + (size_t)row * N + col);
                    *(float2*)(Dout + rowoff + col) =
                        make_float2(w * tanhf(d0 + e.x), w * tanhf(d1 + e.y));
                } else {
                    if (EPI == EPI_TANH_HILO) { d0 = tanhf(d0); d1 = tanhf(d1); }
                    __nv_bfloat16 h0 = __float2bfloat16(d0), h1 = __float2bfloat16(d1);
                    __nv_bfloat16 l0 = __float2bfloat16(d0 - __bfloat162float(h0));
                    __nv_bfloat16 l1 = __float2bfloat16(d1 - __bfloat162float(h1));
                    uint32_t ph = (uint32_t)__bfloat16_as_ushort(h0) |
                                  ((uint32_t)__bfloat16_as_ushort(h1) << 16);
                    uint32_t pl = (uint32_t)__bfloat16_as_ushort(l0) |
                                  ((uint32_t)__bfloat16_as_ushort(l1) << 16);
                    *(uint32_t*)(Dhi + rowoff + col) = ph;
                    *(uint32_t*)(Dlo + rowoff + col) = pl;
                    if (EPI == EPI_TANH_HILO)
                        *(float2*)(Dout + rowoff + col) = make_float2(d0, d1);
                }
            }
        }
    }
}

// ---------------- transpose + bf16 hi/lo split ----------------
__global__ void transconv_k(const float* __restrict__ X,
                            __nv_bfloat16* __restrict__ H, __nv_bfloat16* __restrict__ L,
                            int R, int C)
{
    __shared__ float tile[32][33];
    const int bz = blockIdx.z;
    const float* Xb = X + (size_t)bz * R * C;
    const int x0 = blockIdx.x * 32, y0 = blockIdx.y * 32;
    const int tx = threadIdx.x, ty = threadIdx.y;
#pragma unroll
    for (int j = 0; j < 4; j++)
        tile[ty + j * 8][tx] = Xb[(size_t)(y0 + ty + j * 8) * C + x0 + tx];
    __syncthreads();
    __nv_bfloat16* Hb = H + (size_t)bz * R * C;
    __nv_bfloat16* Lb = L + (size_t)bz * R * C;
#pragma unroll
    for (int j = 0; j < 4; j++) {
        float v = tile[tx][ty + j * 8];
        size_t o = (size_t)(x0 + ty + j * 8) * R + y0 + tx;
        __nv_bfloat16 h = __float2bfloat16(v);
        Hb[o] = h;
        Lb[o] = __float2bfloat16(v - __bfloat162float(h));
    }
}

__global__ void wconv_all_k(const float* __restrict__ Wb, const float* __restrict__ Wq,
                            const float* __restrict__ Wv)
{
    int i = blockIdx.x * blockDim.x + threadIdx.x;
    int which = blockIdx.y;
    const float* X = (which == 0) ? Wb : (which == 1) ? Wq : Wv;
    __nv_bfloat16* H = (which == 0) ? g_Wb_hi : (which == 1) ? g_Wq_hi : g_Wv_hi;
    __nv_bfloat16* L = (which == 0) ? g_Wb_lo : (which == 1) ? g_Wq_lo : g_Wv_lo;
    float v = X[i];
    __nv_bfloat16 h = __float2bfloat16(v);
    H[i] = h;
    L[i] = __float2bfloat16(v - __bfloat162float(h));
}

__global__ void col_reduce_k(const float* __restrict__ G)
{
    int t = blockIdx.x * blockDim.x + threadIdx.x;
    int b = blockIdx.y;
    const float* g = G + (size_t)b * F_ * T_ + t;
    float acc = 0.0f;
#pragma unroll 8
    for (int f = 0; f < F_; f++) acc += g[(size_t)f * T_];
    g_logit[b * T_ + t] = acc;
}

__global__ void softmax_k(float* __restrict__ aq)
{
    __shared__ float sm[256];
    int b = blockIdx.x, tid = threadIdx.x;
    const float* lg = g_logit + b * T_;
    float v[4]; float vmax = -1e30f;
#pragma unroll
    for (int i = 0; i < 4; i++) { v[i] = lg[tid + i * 256]; vmax = fmaxf(vmax, v[i]); }
    sm[tid] = vmax; __syncthreads();
    for (int s = 128; s > 0; s >>= 1) { if (tid < s) sm[tid] = fmaxf(sm[tid], sm[tid + s]); __syncthreads(); }
    vmax = sm[0]; __syncthreads();
    float lsum = 0.0f;
#pragma unroll
    for (int i = 0; i < 4; i++) { v[i] = expf(v[i] - vmax); lsum += v[i]; }
    sm[tid] = lsum; __syncthreads();
    for (int s = 128; s > 0; s >>= 1) { if (tid < s) sm[tid] += sm[tid + s]; __syncthreads(); }
    float inv = 1.0f / sm[0];
#pragma unroll
    for (int i = 0; i < 4; i++) aq[b * T_ + tid + i * 256] = v[i] * inv;
}

__global__ void attn_k(const float* __restrict__ zr, const float* __restrict__ aq,
                       float* __restrict__ out)
{
    int gwarp = (blockIdx.x * blockDim.x + threadIdx.x) >> 5;
    int lane = threadIdx.x & 31;
    int b = gwarp >> 9, s = gwarp & (S_ - 1);
    const float* z = zr + ((size_t)b * S_ + s) * T_;
    const float* a = aq + b * T_;
    float acc = 0.0f;
#pragma unroll 4
    for (int t = lane; t < T_; t += 32) acc += z[t] * a[t];
#pragma unroll
    for (int o = 16; o > 0; o >>= 1) acc += __shfl_xor_sync(0xFFFFFFFFu, acc, o);
    if (lane == 0) out[b * S_ + s] = acc;
}

extern "C" void kernel_launch(void* const* d_in, const int* in_sizes, int n_in,
                              void* d_out, int out_size)
{
    const float* zr  = (const float*)d_in[0];
    const float* zh  = (const float*)d_in[1];
    const float* Wb  = (const float*)d_in[2];
    const float* Wq  = (const float*)d_in[3];
    const float* Wv  = (const float*)d_in[4];
    const float* whq = (const float*)d_in[5];

    float* out  = (float*)d_out;
    float* attn = out;
    float* aq   = out + B_ * S_;
    float* Cmat = out + B_ * S_ + B_ * T_;

    cudaFuncSetAttribute(mma_gemm<EPI_NONE>,      cudaFuncAttributeMaxDynamicSharedMemorySize, GEMM_SMEM);
    cudaFuncSetAttribute(mma_gemm<EPI_HILO>,      cudaFuncAttributeMaxDynamicSharedMemorySize, GEMM_SMEM);
    cudaFuncSetAttribute(mma_gemm<EPI_TANH_HILO>, cudaFuncAttributeMaxDynamicSharedMemorySize, GEMM_SMEM);
    cudaFuncSetAttribute(mma_gemm<EPI_WG>,        cudaFuncAttributeMaxDynamicSharedMemorySize, GEMM_SMEM);

    __nv_bfloat16 *zhT_hi, *zhT_lo, *zrT_hi, *zrT_lo, *auxT_hi, *auxT_lo;
    __nv_bfloat16 *C_hi, *C_lo, *a2_hi, *a2_lo;
    __nv_bfloat16 *Wb_hi, *Wb_lo, *Wq_hi, *Wq_lo, *Wv_hi, *Wv_lo;
    float *a3, *G;
    cudaGetSymbolAddress((void**)&zhT_hi, g_zhT_hi);   cudaGetSymbolAddress((void**)&zhT_lo, g_zhT_lo);
    cudaGetSymbolAddress((void**)&zrT_hi, g_zrT_hi);   cudaGetSymbolAddress((void**)&zrT_lo, g_zrT_lo);
    cudaGetSymbolAddress((void**)&auxT_hi, g_auxT_hi); cudaGetSymbolAddress((void**)&auxT_lo, g_auxT_lo);
    cudaGetSymbolAddress((void**)&C_hi, g_C_hi);       cudaGetSymbolAddress((void**)&C_lo, g_C_lo);
    cudaGetSymbolAddress((void**)&a2_hi, g_a2_hi);     cudaGetSymbolAddress((void**)&a2_lo, g_a2_lo);
    cudaGetSymbolAddress((void**)&Wb_hi, g_Wb_hi);     cudaGetSymbolAddress((void**)&Wb_lo, g_Wb_lo);
    cudaGetSymbolAddress((void**)&Wq_hi, g_Wq_hi);     cudaGetSymbolAddress((void**)&Wq_lo, g_Wq_lo);
    cudaGetSymbolAddress((void**)&Wv_hi, g_Wv_hi);     cudaGetSymbolAddress((void**)&Wv_lo, g_Wv_lo);
    cudaGetSymbolAddress((void**)&a3, g_a3);           cudaGetSymbolAddress((void**)&G, g_G);

    const long TS = (long)T_ * S_;
    const long TT = (long)T_ * T_;
    const long FT = (long)F_ * T_;

    wconv_all_k<<<dim3((F_*S_)/256, 3), 256>>>(Wb, Wq, Wv);
    dim3 tb(32, 8);
    transconv_k<<<dim3(T_/32, S_/32, B_), tb>>>(zh, zhT_hi, zhT_lo, S_, T_);
    transconv_k<<<dim3(T_/32, S_/32, B_), tb>>>(zr, zrT_hi, zrT_lo, S_, T_);

    // G1: auxT[h][s] = sum_u zhT[h][u] * Wb[s][u]         M=T, N=S, K=S
    mma_gemm<EPI_HILO><<<dim3(S_/BN, T_/BM, B_), 256, GEMM_SMEM>>>(
        zhT_hi, zhT_lo, Wb_hi, Wb_lo, nullptr, auxT_hi, auxT_lo, nullptr, nullptr,
        T_, S_, S_, TS, 0L, TS, 0L);

    // G2: C[t][h] = tanh( sum_s zrT[t][s] * auxT[h][s] )  M=T, N=T, K=S
    mma_gemm<EPI_TANH_HILO><<<dim3(T_/BN, T_/BM, B_), 256, GEMM_SMEM>>>(
        zrT_hi, zrT_lo, auxT_hi, auxT_lo, Cmat, C_hi, C_lo, nullptr, nullptr,
        T_, T_, S_, TS, TS, TT, 0L);

    // G3: aux2[f][h] = sum_s Wv[f][s] * zhT[h][s]         M=F, N=T, K=S
    mma_gemm<EPI_HILO><<<dim3(T_/BN, F_/BM, B_), 256, GEMM_SMEM>>>(
        Wv_hi, Wv_lo, zhT_hi, zhT_lo, nullptr, a2_hi, a2_lo, nullptr, nullptr,
        F_, T_, S_, 0L, TS, FT, 0L);

    // G4: aux3[f][t] = sum_s Wq[f][s] * zrT[t][s]         M=F, N=T, K=S
    mma_gemm<EPI_NONE><<<dim3(T_/BN, F_/BM, B_), 256, GEMM_SMEM>>>(
        Wq_hi, Wq_lo, zrT_hi, zrT_lo, a3, nullptr, nullptr, nullptr, nullptr,
        F_, T_, S_, 0L, TS, FT, 0L);

    // G5: G[f][t] = w_hq[f] * tanh( aux3 + sum_h aux2[f][h]*C[t][h] )  M=F, N=T, K=T
    mma_gemm<EPI_WG><<<dim3(T_/BN, F_/BM, B_), 256, GEMM_SMEM>>>(
        a2_hi, a2_lo, C_hi, C_lo, G, nullptr, nullptr, a3, whq,
        F_, T_, T_, FT, TT, FT, FT);

    col_reduce_k<<<dim3(T_/256, B_), 256>>>(G);
    softmax_k<<<B_, 256>>>(aq);
    attn_k<<<(B_ * S_ * 32) / 256, 256>>>(zr, aq, attn);
}

// round 6
// speedup vs baseline: 2.8479x; 1.0347x over previous
#include <cuda_runtime.h>
#include <cuda_bf16.h>
#include <cstdint>
#include <math.h>

#define B_ 32
#define S_ 512
#define F_ 512
#define T_ 1024

#define BM 128
#define BN 128
#define BK 32
#define TILE_B   10240
#define STAGE_B  (4 * TILE_B)
#define NSTAGE   2
#define GEMM_SMEM (NSTAGE * STAGE_B)    // 80 KB -> 2 CTAs/SM
#define LDS_ROW  80

// ---------------- scratch (allocation-free) ----------------
__device__ __nv_bfloat16 g_zhT_hi[(size_t)B_*T_*S_];
__device__ __nv_bfloat16 g_zhT_lo[(size_t)B_*T_*S_];
__device__ __nv_bfloat16 g_zrT_hi[(size_t)B_*T_*S_];
__device__ __nv_bfloat16 g_zrT_lo[(size_t)B_*T_*S_];
__device__ __nv_bfloat16 g_auxT_hi[(size_t)B_*T_*S_];
__device__ __nv_bfloat16 g_auxT_lo[(size_t)B_*T_*S_];
__device__ __nv_bfloat16 g_C_hi[(size_t)B_*T_*T_];
__device__ __nv_bfloat16 g_C_lo[(size_t)B_*T_*T_];
__device__ __nv_bfloat16 g_a2_hi[(size_t)B_*F_*T_];
__device__ __nv_bfloat16 g_a2_lo[(size_t)B_*F_*T_];
__device__ float g_a3[(size_t)B_*F_*T_];
__device__ __nv_bfloat16 g_Wb_hi[S_*S_], g_Wb_lo[S_*S_];
__device__ __nv_bfloat16 g_Wq_hi[F_*S_], g_Wq_lo[F_*S_];
__device__ __nv_bfloat16 g_Wv_hi[F_*S_], g_Wv_lo[F_*S_];
__device__ float g_logit[B_*T_];

// ---------------- helpers ----------------
static __device__ __forceinline__ uint32_t s2u(const void* p){
    uint32_t a;
    asm("{ .reg .u64 t; cvta.to.shared.u64 t, %1; cvt.u32.u64 %0, t; }" : "=r"(a) : "l"(p));
    return a;
}
static __device__ __forceinline__ void cp16(uint32_t dst, const void* src){
    asm volatile("cp.async.cg.shared.global [%0], [%1], 16;" :: "r"(dst), "l"(src) : "memory");
}
static __device__ __forceinline__ void cp_commit(){
    asm volatile("cp.async.commit_group;" ::: "memory");
}
static __device__ __forceinline__ void ldm_x4(uint32_t& r0, uint32_t& r1, uint32_t& r2, uint32_t& r3, uint32_t a){
    asm volatile("ldmatrix.sync.aligned.m8n8.x4.shared.b16 {%0,%1,%2,%3}, [%4];"
                 : "=r"(r0), "=r"(r1), "=r"(r2), "=r"(r3) : "r"(a));
}
static __device__ __forceinline__ void mma16816(float* d, const uint32_t* a, const uint32_t* b){
    asm volatile("mma.sync.aligned.m16n8k16.row.col.f32.bf16.bf16.f32 "
                 "{%0,%1,%2,%3}, {%4,%5,%6,%7}, {%8,%9}, {%0,%1,%2,%3};"
                 : "+f"(d[0]), "+f"(d[1]), "+f"(d[2]), "+f"(d[3])
                 : "r"(a[0]), "r"(a[1]), "r"(a[2]), "r"(a[3]), "r"(b[0]), "r"(b[1]));
}

enum { EPI_NONE = 0, EPI_HILO = 1, EPI_TANH_HILO = 2, EPI_WG_RED = 3 };

// ---------------------------------------------------------------------------
// Shared mainloop: bf16 mma.sync, 3-term hi/lo compensation, 2-stage cp.async.
// KK is the compile-time K. Accumulators in acc[4][4][4].
// ---------------------------------------------------------------------------
template <int KK>
static __device__ __forceinline__ void gemm_main(
    const __nv_bfloat16* __restrict__ sAh, const __nv_bfloat16* __restrict__ sAl,
    const __nv_bfloat16* __restrict__ sBh, const __nv_bfloat16* __restrict__ sBl,
    char* smem, uint32_t sb, int tid, int m0, int n0, float (&acc)[4][4][4])
{
    const int wid = tid >> 5, lane = tid & 31;

    const __nv_bfloat16* gsrc[8];
    uint32_t sdst[8];
#pragma unroll
    for (int u = 0; u < 8; u++) {
        int unit = tid + u * 256;
        int t = unit >> 9;
        int r = (unit >> 2) & 127;
        int c = unit & 3;
        const __nv_bfloat16* base = (t == 0) ? sAh : (t == 1) ? sAl : (t == 2) ? sBh : sBl;
        int row0 = (t < 2) ? m0 : n0;
        gsrc[u] = base + (size_t)(row0 + r) * KK + c * 8;
        sdst[u] = sb + t * TILE_B + r * LDS_ROW + c * 16;
    }

    const int wm = (wid >> 2) * 64;
    const int wn = (wid & 3) * 32;

    uint32_t a_addr[4];
#pragma unroll
    for (int mf = 0; mf < 4; mf++)
        a_addr[mf] = sb + (wm + mf * 16 + (lane & 15)) * LDS_ROW + (lane >> 4) * 16;
    uint32_t b_addr[2];
#pragma unroll
    for (int nt = 0; nt < 2; nt++)
        b_addr[nt] = sb + (wn + nt * 16 + (lane & 7) + ((lane & 16) >> 1)) * LDS_ROW
                   + ((lane >> 3) & 1) * 16;

    const int NC = KK / BK;

#pragma unroll
    for (int u = 0; u < 8; u++) cp16(sdst[u], gsrc[u]);
    cp_commit();
#pragma unroll
    for (int u = 0; u < 8; u++) cp16(sdst[u] + STAGE_B, gsrc[u] + BK);
    cp_commit();

    for (int i = 0; i < NC; i++) {
        if (i + 1 < NC) asm volatile("cp.async.wait_group 1;" ::: "memory");
        else            asm volatile("cp.async.wait_group 0;" ::: "memory");
        __syncthreads();

        const uint32_t stg = (uint32_t)(i & 1) * STAGE_B;

#pragma unroll
        for (int ks = 0; ks < 2; ks++) {
            const uint32_t kb = stg + ks * 32;

            uint32_t bh[4][2], bl[4][2];
#pragma unroll
            for (int nt = 0; nt < 2; nt++) {
                ldm_x4(bh[nt*2][0], bh[nt*2][1], bh[nt*2+1][0], bh[nt*2+1][1],
                       b_addr[nt] + 2 * TILE_B + kb);
                ldm_x4(bl[nt*2][0], bl[nt*2][1], bl[nt*2+1][0], bl[nt*2+1][1],
                       b_addr[nt] + 3 * TILE_B + kb);
            }

            uint32_t ah[4], ahn[4], al[4];
            ldm_x4(ah[0], ah[1], ah[2], ah[3], a_addr[0] + kb);
#pragma unroll
            for (int mf = 0; mf < 4; mf++) {
                if (mf + 1 < 4)
                    ldm_x4(ahn[0], ahn[1], ahn[2], ahn[3], a_addr[mf+1] + kb);
#pragma unroll
                for (int nf = 0; nf < 4; nf++) mma16816(acc[mf][nf], ah, bh[nf]);
                ldm_x4(al[0], al[1], al[2], al[3], a_addr[mf] + TILE_B + kb);
#pragma unroll
                for (int nf = 0; nf < 4; nf++) mma16816(acc[mf][nf], ah, bl[nf]);
#pragma unroll
                for (int nf = 0; nf < 4; nf++) mma16816(acc[mf][nf], al, bh[nf]);
#pragma unroll
                for (int q = 0; q < 4; q++) ah[q] = ahn[q];
            }
        }
        __syncthreads();

        if (i + 2 < NC) {
            const uint32_t dst = (uint32_t)((i + 2) & 1) * STAGE_B;
            const int koff = (i + 2) * BK;
#pragma unroll
            for (int u = 0; u < 8; u++) cp16(sdst[u] + dst, gsrc[u] + koff);
            cp_commit();
        }
    }
}

// ---------------------------------------------------------------------------
// Merged kernel: G1 + G3 + G4 (independent, K=512) in one launch.
// Grid: 3 * B * 32 CTAs linear in blockIdx.x.
// ---------------------------------------------------------------------------
struct MultiDesc {
    const __nv_bfloat16* Ah[3]; const __nv_bfloat16* Al[3];
    const __nv_bfloat16* Bh[3]; const __nv_bfloat16* Bl[3];
    float* Dout[3]; __nv_bfloat16* Dhi[3]; __nv_bfloat16* Dlo[3];
    long sA[3], sB[3], sD[3];
    int N[3], gxlog[3], epi[3];
};

__global__ __launch_bounds__(256, 2)
void mma_multi(MultiDesc d)
{
    extern __shared__ char smem[];
    const uint32_t sb = s2u(smem);
    const int tid = threadIdx.x;
    const int x = blockIdx.x;
    const int gid = x >> 10;             // 1024 CTAs per gemm
    const int rem = x & 1023;
    const int b = rem >> 5;
    const int t = rem & 31;
    const int gxl = d.gxlog[gid];
    const int bx = t & ((1 << gxl) - 1);
    const int by = t >> gxl;
    const int m0 = by * BM, n0 = bx * BN;
    const int N = d.N[gid];

    float acc[4][4][4];
#pragma unroll
    for (int i = 0; i < 4; i++)
#pragma unroll
        for (int j = 0; j < 4; j++)
#pragma unroll
            for (int q = 0; q < 4; q++) acc[i][j][q] = 0.0f;

    gemm_main<512>(d.Ah[gid] + (size_t)b * d.sA[gid], d.Al[gid] + (size_t)b * d.sA[gid],
                   d.Bh[gid] + (size_t)b * d.sB[gid], d.Bl[gid] + (size_t)b * d.sB[gid],
                   smem, sb, tid, m0, n0, acc);

    const int wid = tid >> 5, lane = tid & 31;
    const int wm = (wid >> 2) * 64, wn = (wid & 3) * 32;
    const int g = lane >> 2, tg = lane & 3;
    const int epi = d.epi[gid];
    const long sD = d.sD[gid];

#pragma unroll
    for (int mf = 0; mf < 4; mf++) {
#pragma unroll
        for (int h = 0; h < 2; h++) {
            const int row = m0 + wm + mf * 16 + g + h * 8;
            const size_t rowoff = (size_t)b * sD + (size_t)row * N;
#pragma unroll
            for (int nf = 0; nf < 4; nf++) {
                const int col = n0 + wn + nf * 8 + tg * 2;
                float d0 = acc[mf][nf][h * 2 + 0];
                float d1 = acc[mf][nf][h * 2 + 1];
                if (epi == EPI_NONE) {
                    *(float2*)(d.Dout[gid] + rowoff + col) = make_float2(d0, d1);
                } else {
                    __nv_bfloat16 h0 = __float2bfloat16(d0), h1 = __float2bfloat16(d1);
                    __nv_bfloat16 l0 = __float2bfloat16(d0 - __bfloat162float(h0));
                    __nv_bfloat16 l1 = __float2bfloat16(d1 - __bfloat162float(h1));
                    *(uint32_t*)(d.Dhi[gid] + rowoff + col) =
                        (uint32_t)__bfloat16_as_ushort(h0) | ((uint32_t)__bfloat16_as_ushort(h1) << 16);
                    *(uint32_t*)(d.Dlo[gid] + rowoff + col) =
                        (uint32_t)__bfloat16_as_ushort(l0) | ((uint32_t)__bfloat16_as_ushort(l1) << 16);
                }
            }
        }
    }
}

// ---------------------------------------------------------------------------
// Single-GEMM kernel for G2 (TANH_HILO, K=512) and G5 (WG_RED, K=1024).
// ---------------------------------------------------------------------------
template <int EPI, int KK>
__global__ __launch_bounds__(256, 2)
void mma_gemm(const __nv_bfloat16* __restrict__ Ahi, const __nv_bfloat16* __restrict__ Alo,
              const __nv_bfloat16* __restrict__ Bhi, const __nv_bfloat16* __restrict__ Blo,
              float* __restrict__ Dout,
              __nv_bfloat16* __restrict__ Dhi, __nv_bfloat16* __restrict__ Dlo,
              const float* __restrict__ Eadd, const float* __restrict__ wv,
              int N, long sA, long sB, long sD, long sE)
{
    extern __shared__ char smem[];
    const uint32_t sb = s2u(smem);
    const int tid = threadIdx.x;
    const int b = blockIdx.z;
    const int m0 = blockIdx.y * BM, n0 = blockIdx.x * BN;

    float acc[4][4][4];
#pragma unroll
    for (int i = 0; i < 4; i++)
#pragma unroll
        for (int j = 0; j < 4; j++)
#pragma unroll
            for (int q = 0; q < 4; q++) acc[i][j][q] = 0.0f;

    gemm_main<KK>(Ahi + (size_t)b * sA, Alo + (size_t)b * sA,
                  Bhi + (size_t)b * sB, Blo + (size_t)b * sB,
                  smem, sb, tid, m0, n0, acc);

    const int wid = tid >> 5, lane = tid & 31;
    const int wm = (wid >> 2) * 64, wn = (wid & 3) * 32;
    const int g = lane >> 2, tg = lane & 3;

    if (EPI == EPI_TANH_HILO) {
#pragma unroll
        for (int mf = 0; mf < 4; mf++) {
#pragma unroll
            for (int h = 0; h < 2; h++) {
                const int row = m0 + wm + mf * 16 + g + h * 8;
                const size_t rowoff = (size_t)b * sD + (size_t)row * N;
#pragma unroll
                for (int nf = 0; nf < 4; nf++) {
                    const int col = n0 + wn + nf * 8 + tg * 2;
                    float d0 = tanhf(acc[mf][nf][h * 2 + 0]);
                    float d1 = tanhf(acc[mf][nf][h * 2 + 1]);
                    __nv_bfloat16 h0 = __float2bfloat16(d0), h1 = __float2bfloat16(d1);
                    __nv_bfloat16 l0 = __float2bfloat16(d0 - __bfloat162float(h0));
                    __nv_bfloat16 l1 = __float2bfloat16(d1 - __bfloat162float(h1));
                    *(uint32_t*)(Dhi + rowoff + col) =
                        (uint32_t)__bfloat16_as_ushort(h0) | ((uint32_t)__bfloat16_as_ushort(h1) << 16);
                    *(uint32_t*)(Dlo + rowoff + col) =
                        (uint32_t)__bfloat16_as_ushort(l0) | ((uint32_t)__bfloat16_as_ushort(l1) << 16);
                    *(float2*)(Dout + rowoff + col) = make_float2(d0, d1);
                }
            }
        }
    } else {
        // EPI_WG_RED: logits[b, n] += sum_rows w_hq[row] * tanh(acc + a3[row][n])
        float colsum[8];
#pragma unroll
        for (int q = 0; q < 8; q++) colsum[q] = 0.0f;
#pragma unroll
        for (int mf = 0; mf < 4; mf++) {
#pragma unroll
            for (int h = 0; h < 2; h++) {
                const int row = m0 + wm + mf * 16 + g + h * 8;
                const float w = wv[row];
                const float* ep = Eadd + (size_t)b * sE + (size_t)row * N;
#pragma unroll
                for (int nf = 0; nf < 4; nf++) {
                    const int col = n0 + wn + nf * 8 + tg * 2;
                    const float2 e = *(const float2*)(ep + col);
                    colsum[nf*2+0] += w * tanhf(acc[mf][nf][h * 2 + 0] + e.x);
                    colsum[nf*2+1] += w * tanhf(acc[mf][nf][h * 2 + 1] + e.y);
                }
            }
        }
        float* red = (float*)smem;   // mainloop done; smem reusable
        if (tid < BN) red[tid] = 0.0f;
        __syncthreads();
#pragma unroll
        for (int nf = 0; nf < 4; nf++) {
            atomicAdd(&red[wn + nf * 8 + tg * 2 + 0], colsum[nf*2+0]);
            atomicAdd(&red[wn + nf * 8 + tg * 2 + 1], colsum[nf*2+1]);
        }
        __syncthreads();
        if (tid < BN) atomicAdd(&g_logit[b * T_ + n0 + tid], red[tid]);
    }
}

// ---------------- transpose + bf16 hi/lo split (both z tensors, one launch) --
__global__ void transconv2_k(const float* __restrict__ Zh, const float* __restrict__ Zr)
{
    __shared__ float tile[32][33];
    const int bz = blockIdx.z;           // 0..2B-1
    const int which = bz >> 5;           // 0: zh, 1: zr
    const int bb = bz & 31;
    const float* Xb = ((which == 0) ? Zh : Zr) + (size_t)bb * S_ * T_;
    __nv_bfloat16* H = ((which == 0) ? g_zhT_hi : g_zrT_hi) + (size_t)bb * T_ * S_;
    __nv_bfloat16* L = ((which == 0) ? g_zhT_lo : g_zrT_lo) + (size_t)bb * T_ * S_;
    const int x0 = blockIdx.x * 32, y0 = blockIdx.y * 32;
    const int tx = threadIdx.x, ty = threadIdx.y;
#pragma unroll
    for (int j = 0; j < 4; j++)
        tile[ty + j * 8][tx] = Xb[(size_t)(y0 + ty + j * 8) * T_ + x0 + tx];
    __syncthreads();
#pragma unroll
    for (int j = 0; j < 4; j++) {
        float v = tile[tx][ty + j * 8];
        size_t o = (size_t)(x0 + ty + j * 8) * S_ + y0 + tx;
        __nv_bfloat16 h = __float2bfloat16(v);
        H[o] = h;
        L[o] = __float2bfloat16(v - __bfloat162float(h));
    }
}

__global__ void wconv_all_k(const float* __restrict__ Wb, const float* __restrict__ Wq,
                            const float* __restrict__ Wv)
{
    int i = blockIdx.x * blockDim.x + threadIdx.x;
    int which = blockIdx.y;
    const float* X = (which == 0) ? Wb : (which == 1) ? Wq : Wv;
    __nv_bfloat16* H = (which == 0) ? g_Wb_hi : (which == 1) ? g_Wq_hi : g_Wv_hi;
    __nv_bfloat16* L = (which == 0) ? g_Wb_lo : (which == 1) ? g_Wq_lo : g_Wv_lo;
    float v = X[i];
    __nv_bfloat16 h = __float2bfloat16(v);
    H[i] = h;
    L[i] = __float2bfloat16(v - __bfloat162float(h));
    if (which == 0 && i < B_ * T_) g_logit[i] = 0.0f;   // zero logits for G5's atomics
}

__global__ void softmax_k(float* __restrict__ aq)
{
    __shared__ float sm[256];
    int b = blockIdx.x, tid = threadIdx.x;
    const float* lg = g_logit + b * T_;
    float v[4]; float vmax = -1e30f;
#pragma unroll
    for (int i = 0; i < 4; i++) { v[i] = lg[tid + i * 256]; vmax = fmaxf(vmax, v[i]); }
    sm[tid] = vmax; __syncthreads();
    for (int s = 128; s > 0; s >>= 1) { if (tid < s) sm[tid] = fmaxf(sm[tid], sm[tid + s]); __syncthreads(); }
    vmax = sm[0]; __syncthreads();
    float lsum = 0.0f;
#pragma unroll
    for (int i = 0; i < 4; i++) { v[i] = expf(v[i] - vmax); lsum += v[i]; }
    sm[tid] = lsum; __syncthreads();
    for (int s = 128; s > 0; s >>= 1) { if (tid < s) sm[tid] += sm[tid + s]; __syncthreads(); }
    float inv = 1.0f / sm[0];
#pragma unroll
    for (int i = 0; i < 4; i++) aq[b * T_ + tid + i * 256] = v[i] * inv;
}

__global__ void attn_k(const float* __restrict__ zr, const float* __restrict__ aq,
                       float* __restrict__ out)
{
    int gwarp = (blockIdx.x * blockDim.x + threadIdx.x) >> 5;
    int lane = threadIdx.x & 31;
    int b = gwarp >> 9, s = gwarp & (S_ - 1);
    const float* z = zr + ((size_t)b * S_ + s) * T_;
    const float* a = aq + b * T_;
    float acc = 0.0f;
#pragma unroll 4
    for (int t = lane; t < T_; t += 32) acc += z[t] * a[t];
#pragma unroll
    for (int o = 16; o > 0; o >>= 1) acc += __shfl_xor_sync(0xFFFFFFFFu, acc, o);
    if (lane == 0) out[b * S_ + s] = acc;
}

extern "C" void kernel_launch(void* const* d_in, const int* in_sizes, int n_in,
                              void* d_out, int out_size)
{
    const float* zr  = (const float*)d_in[0];
    const float* zh  = (const float*)d_in[1];
    const float* Wb  = (const float*)d_in[2];
    const float* Wq  = (const float*)d_in[3];
    const float* Wv  = (const float*)d_in[4];
    const float* whq = (const float*)d_in[5];

    float* out  = (float*)d_out;
    float* attn = out;
    float* aq   = out + B_ * S_;
    float* Cmat = out + B_ * S_ + B_ * T_;

    cudaFuncSetAttribute(mma_multi, cudaFuncAttributeMaxDynamicSharedMemorySize, GEMM_SMEM);
    cudaFuncSetAttribute(mma_gemm<EPI_TANH_HILO, 512>,  cudaFuncAttributeMaxDynamicSharedMemorySize, GEMM_SMEM);
    cudaFuncSetAttribute(mma_gemm<EPI_WG_RED, 1024>,    cudaFuncAttributeMaxDynamicSharedMemorySize, GEMM_SMEM);

    __nv_bfloat16 *zhT_hi, *zhT_lo, *zrT_hi, *zrT_lo, *auxT_hi, *auxT_lo;
    __nv_bfloat16 *C_hi, *C_lo, *a2_hi, *a2_lo;
    __nv_bfloat16 *Wb_hi, *Wb_lo, *Wq_hi, *Wq_lo, *Wv_hi, *Wv_lo;
    float *a3;
    cudaGetSymbolAddress((void**)&zhT_hi, g_zhT_hi);   cudaGetSymbolAddress((void**)&zhT_lo, g_zhT_lo);
    cudaGetSymbolAddress((void**)&zrT_hi, g_zrT_hi);   cudaGetSymbolAddress((void**)&zrT_lo, g_zrT_lo);
    cudaGetSymbolAddress((void**)&auxT_hi, g_auxT_hi); cudaGetSymbolAddress((void**)&auxT_lo, g_auxT_lo);
    cudaGetSymbolAddress((void**)&C_hi, g_C_hi);       cudaGetSymbolAddress((void**)&C_lo, g_C_lo);
    cudaGetSymbolAddress((void**)&a2_hi, g_a2_hi);     cudaGetSymbolAddress((void**)&a2_lo, g_a2_lo);
    cudaGetSymbolAddress((void**)&Wb_hi, g_Wb_hi);     cudaGetSymbolAddress((void**)&Wb_lo, g_Wb_lo);
    cudaGetSymbolAddress((void**)&Wq_hi, g_Wq_hi);     cudaGetSymbolAddress((void**)&Wq_lo, g_Wq_lo);
    cudaGetSymbolAddress((void**)&Wv_hi, g_Wv_hi);     cudaGetSymbolAddress((void**)&Wv_lo, g_Wv_lo);
    cudaGetSymbolAddress((void**)&a3, g_a3);

    const long TS = (long)T_ * S_;
    const long TT = (long)T_ * T_;
    const long FT = (long)F_ * T_;

    wconv_all_k<<<dim3((F_*S_)/256, 3), 256>>>(Wb, Wq, Wv);
    transconv2_k<<<dim3(T_/32, S_/32, 2*B_), dim3(32, 8)>>>(zh, zr);

    // Merged G1+G3+G4 (all K=512, independent):
    //  G1: auxT[h][s] = sum_u zhT[h][u] * Wb[s][u]   (M=1024, N=512)
    //  G3: aux2[f][h] = sum_s Wv[f][s] * zhT[h][s]   (M=512, N=1024)
    //  G4: aux3[f][t] = sum_s Wq[f][s] * zrT[t][s]   (M=512, N=1024)
    MultiDesc md;
    md.Ah[0]=zhT_hi; md.Al[0]=zhT_lo; md.Bh[0]=Wb_hi;  md.Bl[0]=Wb_lo;
    md.Dout[0]=nullptr; md.Dhi[0]=auxT_hi; md.Dlo[0]=auxT_lo;
    md.sA[0]=TS; md.sB[0]=0; md.sD[0]=TS; md.N[0]=S_; md.gxlog[0]=2; md.epi[0]=EPI_HILO;

    md.Ah[1]=Wv_hi;  md.Al[1]=Wv_lo;  md.Bh[1]=zhT_hi; md.Bl[1]=zhT_lo;
    md.Dout[1]=nullptr; md.Dhi[1]=a2_hi; md.Dlo[1]=a2_lo;
    md.sA[1]=0; md.sB[1]=TS; md.sD[1]=FT; md.N[1]=T_; md.gxlog[1]=3; md.epi[1]=EPI_HILO;

    md.Ah[2]=Wq_hi;  md.Al[2]=Wq_lo;  md.Bh[2]=zrT_hi; md.Bl[2]=zrT_lo;
    md.Dout[2]=a3; md.Dhi[2]=nullptr; md.Dlo[2]=nullptr;
    md.sA[2]=0; md.sB[2]=TS; md.sD[2]=FT; md.N[2]=T_; md.gxlog[2]=3; md.epi[2]=EPI_NONE;

    mma_multi<<<3 * B_ * 32, 256, GEMM_SMEM>>>(md);

    // G2: C[t][h] = tanh( sum_s zrT[t][s] * auxT[h][s] )   M=N=1024, K=512
    mma_gemm<EPI_TANH_HILO, 512><<<dim3(T_/BN, T_/BM, B_), 256, GEMM_SMEM>>>(
        zrT_hi, zrT_lo, auxT_hi, auxT_lo, Cmat, C_hi, C_lo, nullptr, nullptr,
        T_, TS, TS, TT, 0L);

    // G5 fused: logits[b,t] = sum_f w_hq[f]*tanh(a3[f,t] + sum_h a2[f,h]*C[t,h])
    mma_gemm<EPI_WG_RED, 1024><<<dim3(T_/BN, F_/BM, B_), 256, GEMM_SMEM>>>(
        a2_hi, a2_lo, C_hi, C_lo, nullptr, nullptr, nullptr, a3, whq,
        T_, FT, TT, 0L, FT);

    softmax_k<<<B_, 256>>>(aq);
    attn_k<<<(B_ * S_ * 32) / 256, 256>>>(zr, aq, attn);
}

// round 7
// speedup vs baseline: 3.2658x; 1.1467x over previous
#include <cuda_runtime.h>
#include <cuda_bf16.h>
#include <cstdint>
#include <math.h>

#define B_ 32
#define S_ 512
#define F_ 512
#define T_ 1024

#define BM 128
#define BN 128
#define BK 32
// tile: 128 rows x 64B (swizzled, no pad) = 8KB; 4 tiles/stage; 3 stages = 96KB
#define TILE_B   8192
#define STAGE_B  (4 * TILE_B)
#define NSTAGE   3
#define GEMM_SMEM (NSTAGE * STAGE_B)

// ---------------- scratch (allocation-free) ----------------
__device__ __nv_bfloat16 g_zhT_hi[(size_t)B_*T_*S_];
__device__ __nv_bfloat16 g_zhT_lo[(size_t)B_*T_*S_];
__device__ __nv_bfloat16 g_zrT_hi[(size_t)B_*T_*S_];
__device__ __nv_bfloat16 g_zrT_lo[(size_t)B_*T_*S_];
__device__ __nv_bfloat16 g_auxT_hi[(size_t)B_*T_*S_];
__device__ __nv_bfloat16 g_auxT_lo[(size_t)B_*T_*S_];
__device__ __nv_bfloat16 g_C_hi[(size_t)B_*T_*T_];
__device__ __nv_bfloat16 g_C_lo[(size_t)B_*T_*T_];
__device__ __nv_bfloat16 g_a2_hi[(size_t)B_*F_*T_];
__device__ __nv_bfloat16 g_a2_lo[(size_t)B_*F_*T_];
__device__ float g_a3[(size_t)B_*F_*T_];
__device__ __nv_bfloat16 g_Wb_hi[S_*S_], g_Wb_lo[S_*S_];
__device__ __nv_bfloat16 g_Wq_hi[F_*S_], g_Wq_lo[F_*S_];
__device__ __nv_bfloat16 g_Wv_hi[F_*S_], g_Wv_lo[F_*S_];
__device__ float g_logit[B_*T_];

// ---------------- helpers ----------------
static __device__ __forceinline__ uint32_t s2u(const void* p){
    uint32_t a;
    asm("{ .reg .u64 t; cvta.to.shared.u64 t, %1; cvt.u32.u64 %0, t; }" : "=r"(a) : "l"(p));
    return a;
}
static __device__ __forceinline__ void cp16(uint32_t dst, const void* src){
    asm volatile("cp.async.cg.shared.global [%0], [%1], 16;" :: "r"(dst), "l"(src) : "memory");
}
static __device__ __forceinline__ void cp_commit(){
    asm volatile("cp.async.commit_group;" ::: "memory");
}
static __device__ __forceinline__ void ldm_x4(uint32_t& r0, uint32_t& r1, uint32_t& r2, uint32_t& r3, uint32_t a){
    asm volatile("ldmatrix.sync.aligned.m8n8.x4.shared.b16 {%0,%1,%2,%3}, [%4];"
                 : "=r"(r0), "=r"(r1), "=r"(r2), "=r"(r3) : "r"(a));
}
static __device__ __forceinline__ void mma16816(float* d, const uint32_t* a, const uint32_t* b){
    asm volatile("mma.sync.aligned.m16n8k16.row.col.f32.bf16.bf16.f32 "
                 "{%0,%1,%2,%3}, {%4,%5,%6,%7}, {%8,%9}, {%0,%1,%2,%3};"
                 : "+f"(d[0]), "+f"(d[1]), "+f"(d[2]), "+f"(d[3])
                 : "r"(a[0]), "r"(a[1]), "r"(a[2]), "r"(a[3]), "r"(b[0]), "r"(b[1]));
}

enum { EPI_NONE = 0, EPI_HILO = 1, EPI_TANH_HILO = 2, EPI_WG_RED = 3 };

// Swizzle: 64B rows, 4x16B chunks; chunk' = chunk ^ ((row>>1)&3).
// Conflict-free for cp.async 16B stores and all ldmatrix read patterns.

// ---------------------------------------------------------------------------
// Shared mainloop: bf16 mma.sync, 3-term hi/lo compensation,
// 3-stage cp.async pipeline with a single __syncthreads per K-iteration.
// ---------------------------------------------------------------------------
template <int KK>
static __device__ __forceinline__ void gemm_main(
    const __nv_bfloat16* __restrict__ sAh, const __nv_bfloat16* __restrict__ sAl,
    const __nv_bfloat16* __restrict__ sBh, const __nv_bfloat16* __restrict__ sBl,
    uint32_t sb, int tid, int m0, int n0, float (&acc)[4][4][4])
{
    const int wid = tid >> 5, lane = tid & 31;

    // loader geometry: 2048 16B units per stage (4 tiles x 512), 8 per thread
    const __nv_bfloat16* gsrc[8];
    uint32_t sdst[8];
#pragma unroll
    for (int u = 0; u < 8; u++) {
        int unit = tid + u * 256;
        int t = unit >> 9;
        int r = (unit >> 2) & 127;
        int c = unit & 3;
        const __nv_bfloat16* base = (t == 0) ? sAh : (t == 1) ? sAl : (t == 2) ? sBh : sBl;
        int row0 = (t < 2) ? m0 : n0;
        gsrc[u] = base + (size_t)(row0 + r) * KK + c * 8;
        sdst[u] = sb + t * TILE_B + r * 64 + ((c ^ ((r >> 1) & 3)) * 16);
    }

    const int wm = (wid >> 2) * 64;
    const int wn = (wid & 3) * 32;

    // ldmatrix row bases + per-row swizzle keys
    uint32_t a_row[4]; int a_sw[4];
    const int a_cb = lane >> 4;                 // chunk half within 32B k-step
#pragma unroll
    for (int mf = 0; mf < 4; mf++) {
        int row = wm + mf * 16 + (lane & 15);
        a_row[mf] = sb + row * 64;
        a_sw[mf] = (row >> 1) & 3;
    }
    uint32_t b_row[2]; int b_sw[2];
    const int b_cb = (lane >> 3) & 1;
#pragma unroll
    for (int nt = 0; nt < 2; nt++) {
        int row = wn + nt * 16 + (lane & 7) + ((lane & 16) >> 1);
        b_row[nt] = sb + row * 64;
        b_sw[nt] = (row >> 1) & 3;
    }

    const int NC = KK / BK;

    // prologue: stages 0, 1
#pragma unroll
    for (int u = 0; u < 8; u++) cp16(sdst[u], gsrc[u]);
    cp_commit();
#pragma unroll
    for (int u = 0; u < 8; u++) cp16(sdst[u] + STAGE_B, gsrc[u] + BK);
    cp_commit();

    int buf = 0;        // i % 3
    int nbuf = 2;       // (i+2) % 3
    for (int i = 0; i < NC; i++) {
        if (i + 1 < NC) asm volatile("cp.async.wait_group 1;" ::: "memory");
        else            asm volatile("cp.async.wait_group 0;" ::: "memory");
        __syncthreads();   // all threads' stage-i data visible; frees buf (i-1)%3

        if (i + 2 < NC) {
            const uint32_t dst = (uint32_t)nbuf * STAGE_B;
            const int koff = (i + 2) * BK;
#pragma unroll
            for (int u = 0; u < 8; u++) cp16(sdst[u] + dst, gsrc[u] + koff);
            cp_commit();
        }

        const uint32_t stg = (uint32_t)buf * STAGE_B;
#pragma unroll
        for (int ks = 0; ks < 2; ks++) {
            const int ac = a_cb + 2 * ks;       // chunk index 0..3
            const int bc = b_cb + 2 * ks;

            uint32_t bh[4][2], bl[4][2];
#pragma unroll
            for (int nt = 0; nt < 2; nt++) {
                const uint32_t badr = b_row[nt] + stg + ((bc ^ b_sw[nt]) * 16);
                ldm_x4(bh[nt*2][0], bh[nt*2][1], bh[nt*2+1][0], bh[nt*2+1][1],
                       badr + 2 * TILE_B);
                ldm_x4(bl[nt*2][0], bl[nt*2][1], bl[nt*2+1][0], bl[nt*2+1][1],
                       badr + 3 * TILE_B);
            }

            uint32_t ah[4], ahn[4], al[4];
            ldm_x4(ah[0], ah[1], ah[2], ah[3],
                   a_row[0] + stg + ((ac ^ a_sw[0]) * 16));
#pragma unroll
            for (int mf = 0; mf < 4; mf++) {
                const uint32_t aadr = a_row[mf] + stg + ((ac ^ a_sw[mf]) * 16);
                if (mf + 1 < 4)
                    ldm_x4(ahn[0], ahn[1], ahn[2], ahn[3],
                           a_row[mf+1] + stg + ((ac ^ a_sw[mf+1]) * 16));
#pragma unroll
                for (int nf = 0; nf < 4; nf++) mma16816(acc[mf][nf], ah, bh[nf]);
                ldm_x4(al[0], al[1], al[2], al[3], aadr + TILE_B);
#pragma unroll
                for (int nf = 0; nf < 4; nf++) mma16816(acc[mf][nf], ah, bl[nf]);
#pragma unroll
                for (int nf = 0; nf < 4; nf++) mma16816(acc[mf][nf], al, bh[nf]);
#pragma unroll
                for (int q = 0; q < 4; q++) ah[q] = ahn[q];
            }
        }

        buf = (buf == 2) ? 0 : buf + 1;
        nbuf = (nbuf == 2) ? 0 : nbuf + 1;
    }
}

// ---------------------------------------------------------------------------
// Merged kernel: G1 + G3 + G4 (independent, K=512) in one launch.
// ---------------------------------------------------------------------------
struct MultiDesc {
    const __nv_bfloat16* Ah[3]; const __nv_bfloat16* Al[3];
    const __nv_bfloat16* Bh[3]; const __nv_bfloat16* Bl[3];
    float* Dout[3]; __nv_bfloat16* Dhi[3]; __nv_bfloat16* Dlo[3];
    long sA[3], sB[3], sD[3];
    int N[3], gxlog[3], epi[3];
};

__global__ __launch_bounds__(256, 2)
void mma_multi(MultiDesc d)
{
    extern __shared__ char smem[];
    const uint32_t sb = s2u(smem);
    const int tid = threadIdx.x;
    const int x = blockIdx.x;
    const int gid = x >> 10;
    const int rem = x & 1023;
    const int b = rem >> 5;
    const int t = rem & 31;
    const int gxl = d.gxlog[gid];
    const int bx = t & ((1 << gxl) - 1);
    const int by = t >> gxl;
    const int m0 = by * BM, n0 = bx * BN;
    const int N = d.N[gid];

    float acc[4][4][4];
#pragma unroll
    for (int i = 0; i < 4; i++)
#pragma unroll
        for (int j = 0; j < 4; j++)
#pragma unroll
            for (int q = 0; q < 4; q++) acc[i][j][q] = 0.0f;

    gemm_main<512>(d.Ah[gid] + (size_t)b * d.sA[gid], d.Al[gid] + (size_t)b * d.sA[gid],
                   d.Bh[gid] + (size_t)b * d.sB[gid], d.Bl[gid] + (size_t)b * d.sB[gid],
                   sb, tid, m0, n0, acc);

    const int wid = tid >> 5, lane = tid & 31;
    const int wm = (wid >> 2) * 64, wn = (wid & 3) * 32;
    const int g = lane >> 2, tg = lane & 3;
    const int epi = d.epi[gid];
    const long sD = d.sD[gid];

#pragma unroll
    for (int mf = 0; mf < 4; mf++) {
#pragma unroll
        for (int h = 0; h < 2; h++) {
            const int row = m0 + wm + mf * 16 + g + h * 8;
            const size_t rowoff = (size_t)b * sD + (size_t)row * N;
#pragma unroll
            for (int nf = 0; nf < 4; nf++) {
                const int col = n0 + wn + nf * 8 + tg * 2;
                float d0 = acc[mf][nf][h * 2 + 0];
                float d1 = acc[mf][nf][h * 2 + 1];
                if (epi == EPI_NONE) {
                    *(float2*)(d.Dout[gid] + rowoff + col) = make_float2(d0, d1);
                } else {
                    __nv_bfloat16 h0 = __float2bfloat16(d0), h1 = __float2bfloat16(d1);
                    __nv_bfloat16 l0 = __float2bfloat16(d0 - __bfloat162float(h0));
                    __nv_bfloat16 l1 = __float2bfloat16(d1 - __bfloat162float(h1));
                    *(uint32_t*)(d.Dhi[gid] + rowoff + col) =
                        (uint32_t)__bfloat16_as_ushort(h0) | ((uint32_t)__bfloat16_as_ushort(h1) << 16);
                    *(uint32_t*)(d.Dlo[gid] + rowoff + col) =
                        (uint32_t)__bfloat16_as_ushort(l0) | ((uint32_t)__bfloat16_as_ushort(l1) << 16);
                }
            }
        }
    }
}

// ---------------------------------------------------------------------------
// Single-GEMM kernel for G2 (TANH_HILO, K=512) and G5 (WG_RED, K=1024).
// ---------------------------------------------------------------------------
template <int EPI, int KK>
__global__ __launch_bounds__(256, 2)
void mma_gemm(const __nv_bfloat16* __restrict__ Ahi, const __nv_bfloat16* __restrict__ Alo,
              const __nv_bfloat16* __restrict__ Bhi, const __nv_bfloat16* __restrict__ Blo,
              float* __restrict__ Dout,
              __nv_bfloat16* __restrict__ Dhi, __nv_bfloat16* __restrict__ Dlo,
              const float* __restrict__ Eadd, const float* __restrict__ wv,
              int N, long sA, long sB, long sD, long sE)
{
    extern __shared__ char smem[];
    const uint32_t sb = s2u(smem);
    const int tid = threadIdx.x;
    const int b = blockIdx.z;
    const int m0 = blockIdx.y * BM, n0 = blockIdx.x * BN;

    float acc[4][4][4];
#pragma unroll
    for (int i = 0; i < 4; i++)
#pragma unroll
        for (int j = 0; j < 4; j++)
#pragma unroll
            for (int q = 0; q < 4; q++) acc[i][j][q] = 0.0f;

    gemm_main<KK>(Ahi + (size_t)b * sA, Alo + (size_t)b * sA,
                  Bhi + (size_t)b * sB, Blo + (size_t)b * sB,
                  sb, tid, m0, n0, acc);

    const int wid = tid >> 5, lane = tid & 31;
    const int wm = (wid >> 2) * 64, wn = (wid & 3) * 32;
    const int g = lane >> 2, tg = lane & 3;

    if (EPI == EPI_TANH_HILO) {
#pragma unroll
        for (int mf = 0; mf < 4; mf++) {
#pragma unroll
            for (int h = 0; h < 2; h++) {
                const int row = m0 + wm + mf * 16 + g + h * 8;
                const size_t rowoff = (size_t)b * sD + (size_t)row * N;
#pragma unroll
                for (int nf = 0; nf < 4; nf++) {
                    const int col = n0 + wn + nf * 8 + tg * 2;
                    float d0 = tanhf(acc[mf][nf][h * 2 + 0]);
                    float d1 = tanhf(acc[mf][nf][h * 2 + 1]);
                    __nv_bfloat16 h0 = __float2bfloat16(d0), h1 = __float2bfloat16(d1);
                    __nv_bfloat16 l0 = __float2bfloat16(d0 - __bfloat162float(h0));
                    __nv_bfloat16 l1 = __float2bfloat16(d1 - __bfloat162float(h1));
                    *(uint32_t*)(Dhi + rowoff + col) =
                        (uint32_t)__bfloat16_as_ushort(h0) | ((uint32_t)__bfloat16_as_ushort(h1) << 16);
                    *(uint32_t*)(Dlo + rowoff + col) =
                        (uint32_t)__bfloat16_as_ushort(l0) | ((uint32_t)__bfloat16_as_ushort(l1) << 16);
                    *(float2*)(Dout + rowoff + col) = make_float2(d0, d1);
                }
            }
        }
    } else {
        // EPI_WG_RED: logits[b, n] += sum_rows w_hq[row] * tanh(acc + a3[row][n])
        float colsum[8];
#pragma unroll
        for (int q = 0; q < 8; q++) colsum[q] = 0.0f;
#pragma unroll
        for (int mf = 0; mf < 4; mf++) {
#pragma unroll
            for (int h = 0; h < 2; h++) {
                const int row = m0 + wm + mf * 16 + g + h * 8;
                const float w = wv[row];
                const float* ep = Eadd + (size_t)b * sE + (size_t)row * N;
#pragma unroll
                for (int nf = 0; nf < 4; nf++) {
                    const int col = n0 + wn + nf * 8 + tg * 2;
                    const float2 e = *(const float2*)(ep + col);
                    colsum[nf*2+0] += w * tanhf(acc[mf][nf][h * 2 + 0] + e.x);
                    colsum[nf*2+1] += w * tanhf(acc[mf][nf][h * 2 + 1] + e.y);
                }
            }
        }
        __syncthreads();   // mainloop reads fully done before smem reuse
        float* red = (float*)smem;
        if (tid < BN) red[tid] = 0.0f;
        __syncthreads();
#pragma unroll
        for (int nf = 0; nf < 4; nf++) {
            atomicAdd(&red[wn + nf * 8 + tg * 2 + 0], colsum[nf*2+0]);
            atomicAdd(&red[wn + nf * 8 + tg * 2 + 1], colsum[nf*2+1]);
        }
        __syncthreads();
        if (tid < BN) atomicAdd(&g_logit[b * T_ + n0 + tid], red[tid]);
    }
}

// ---------------- transpose + bf16 hi/lo split (both z tensors, one launch) --
__global__ void transconv2_k(const float* __restrict__ Zh, const float* __restrict__ Zr)
{
    __shared__ float tile[32][33];
    const int bz = blockIdx.z;
    const int which = bz >> 5;
    const int bb = bz & 31;
    const float* Xb = ((which == 0) ? Zh : Zr) + (size_t)bb * S_ * T_;
    __nv_bfloat16* H = ((which == 0) ? g_zhT_hi : g_zrT_hi) + (size_t)bb * T_ * S_;
    __nv_bfloat16* L = ((which == 0) ? g_zhT_lo : g_zrT_lo) + (size_t)bb * T_ * S_;
    const int x0 = blockIdx.x * 32, y0 = blockIdx.y * 32;
    const int tx = threadIdx.x, ty = threadIdx.y;
#pragma unroll
    for (int j = 0; j < 4; j++)
        tile[ty + j * 8][tx] = Xb[(size_t)(y0 + ty + j * 8) * T_ + x0 + tx];
    __syncthreads();
#pragma unroll
    for (int j = 0; j < 4; j++) {
        float v = tile[tx][ty + j * 8];
        size_t o = (size_t)(x0 + ty + j * 8) * S_ + y0 + tx;
        __nv_bfloat16 h = __float2bfloat16(v);
        H[o] = h;
        L[o] = __float2bfloat16(v - __bfloat162float(h));
    }
}

__global__ void wconv_all_k(const float* __restrict__ Wb, const float* __restrict__ Wq,
                            const float* __restrict__ Wv)
{
    int i = blockIdx.x * blockDim.x + threadIdx.x;
    int which = blockIdx.y;
    const float* X = (which == 0) ? Wb : (which == 1) ? Wq : Wv;
    __nv_bfloat16* H = (which == 0) ? g_Wb_hi : (which == 1) ? g_Wq_hi : g_Wv_hi;
    __nv_bfloat16* L = (which == 0) ? g_Wb_lo : (which == 1) ? g_Wq_lo : g_Wv_lo;
    float v = X[i];
    __nv_bfloat16 h = __float2bfloat16(v);
    H[i] = h;
    L[i] = __float2bfloat16(v - __bfloat162float(h));
    if (which == 0 && i < B_ * T_) g_logit[i] = 0.0f;
}

__global__ void softmax_k(float* __restrict__ aq)
{
    __shared__ float sm[256];
    int b = blockIdx.x, tid = threadIdx.x;
    const float* lg = g_logit + b * T_;
    float v[4]; float vmax = -1e30f;
#pragma unroll
    for (int i = 0; i < 4; i++) { v[i] = lg[tid + i * 256]; vmax = fmaxf(vmax, v[i]); }
    sm[tid] = vmax; __syncthreads();
    for (int s = 128; s > 0; s >>= 1) { if (tid < s) sm[tid] = fmaxf(sm[tid], sm[tid + s]); __syncthreads(); }
    vmax = sm[0]; __syncthreads();
    float lsum = 0.0f;
#pragma unroll
    for (int i = 0; i < 4; i++) { v[i] = expf(v[i] - vmax); lsum += v[i]; }
    sm[tid] = lsum; __syncthreads();
    for (int s = 128; s > 0; s >>= 1) { if (tid < s) sm[tid] += sm[tid + s]; __syncthreads(); }
    float inv = 1.0f / sm[0];
#pragma unroll
    for (int i = 0; i < 4; i++) aq[b * T_ + tid + i * 256] = v[i] * inv;
}

__global__ void attn_k(const float* __restrict__ zr, const float* __restrict__ aq,
                       float* __restrict__ out)
{
    int gwarp = (blockIdx.x * blockDim.x + threadIdx.x) >> 5;
    int lane = threadIdx.x & 31;
    int b = gwarp >> 9, s = gwarp & (S_ - 1);
    const float* z = zr + ((size_t)b * S_ + s) * T_;
    const float* a = aq + b * T_;
    float acc = 0.0f;
#pragma unroll 4
    for (int t = lane; t < T_; t += 32) acc += z[t] * a[t];
#pragma unroll
    for (int o = 16; o > 0; o >>= 1) acc += __shfl_xor_sync(0xFFFFFFFFu, acc, o);
    if (lane == 0) out[b * S_ + s] = acc;
}

extern "C" void kernel_launch(void* const* d_in, const int* in_sizes, int n_in,
                              void* d_out, int out_size)
{
    const float* zr  = (const float*)d_in[0];
    const float* zh  = (const float*)d_in[1];
    const float* Wb  = (const float*)d_in[2];
    const float* Wq  = (const float*)d_in[3];
    const float* Wv  = (const float*)d_in[4];
    const float* whq = (const float*)d_in[5];

    float* out  = (float*)d_out;
    float* attn = out;
    float* aq   = out + B_ * S_;
    float* Cmat = out + B_ * S_ + B_ * T_;

    cudaFuncSetAttribute(mma_multi, cudaFuncAttributeMaxDynamicSharedMemorySize, GEMM_SMEM);
    cudaFuncSetAttribute(mma_gemm<EPI_TANH_HILO, 512>,  cudaFuncAttributeMaxDynamicSharedMemorySize, GEMM_SMEM);
    cudaFuncSetAttribute(mma_gemm<EPI_WG_RED, 1024>,    cudaFuncAttributeMaxDynamicSharedMemorySize, GEMM_SMEM);

    __nv_bfloat16 *zhT_hi, *zhT_lo, *zrT_hi, *zrT_lo, *auxT_hi, *auxT_lo;
    __nv_bfloat16 *C_hi, *C_lo, *a2_hi, *a2_lo;
    __nv_bfloat16 *Wb_hi, *Wb_lo, *Wq_hi, *Wq_lo, *Wv_hi, *Wv_lo;
    float *a3;
    cudaGetSymbolAddress((void**)&zhT_hi, g_zhT_hi);   cudaGetSymbolAddress((void**)&zhT_lo, g_zhT_lo);
    cudaGetSymbolAddress((void**)&zrT_hi, g_zrT_hi);   cudaGetSymbolAddress((void**)&zrT_lo, g_zrT_lo);
    cudaGetSymbolAddress((void**)&auxT_hi, g_auxT_hi); cudaGetSymbolAddress((void**)&auxT_lo, g_auxT_lo);
    cudaGetSymbolAddress((void**)&C_hi, g_C_hi);       cudaGetSymbolAddress((void**)&C_lo, g_C_lo);
    cudaGetSymbolAddress((void**)&a2_hi, g_a2_hi);     cudaGetSymbolAddress((void**)&a2_lo, g_a2_lo);
    cudaGetSymbolAddress((void**)&Wb_hi, g_Wb_hi);     cudaGetSymbolAddress((void**)&Wb_lo, g_Wb_lo);
    cudaGetSymbolAddress((void**)&Wq_hi, g_Wq_hi);     cudaGetSymbolAddress((void**)&Wq_lo, g_Wq_lo);
    cudaGetSymbolAddress((void**)&Wv_hi, g_Wv_hi);     cudaGetSymbolAddress((void**)&Wv_lo, g_Wv_lo);
    cudaGetSymbolAddress((void**)&a3, g_a3);

    const long TS = (long)T_ * S_;
    const long TT = (long)T_ * T_;
    const long FT = (long)F_ * T_;

    wconv_all_k<<<dim3((F_*S_)/256, 3), 256>>>(Wb, Wq, Wv);
    transconv2_k<<<dim3(T_/32, S_/32, 2*B_), dim3(32, 8)>>>(zh, zr);

    MultiDesc md;
    md.Ah[0]=zhT_hi; md.Al[0]=zhT_lo; md.Bh[0]=Wb_hi;  md.Bl[0]=Wb_lo;
    md.Dout[0]=nullptr; md.Dhi[0]=auxT_hi; md.Dlo[0]=auxT_lo;
    md.sA[0]=TS; md.sB[0]=0; md.sD[0]=TS; md.N[0]=S_; md.gxlog[0]=2; md.epi[0]=EPI_HILO;

    md.Ah[1]=Wv_hi;  md.Al[1]=Wv_lo;  md.Bh[1]=zhT_hi; md.Bl[1]=zhT_lo;
    md.Dout[1]=nullptr; md.Dhi[1]=a2_hi; md.Dlo[1]=a2_lo;
    md.sA[1]=0; md.sB[1]=TS; md.sD[1]=FT; md.N[1]=T_; md.gxlog[1]=3; md.epi[1]=EPI_HILO;

    md.Ah[2]=Wq_hi;  md.Al[2]=Wq_lo;  md.Bh[2]=zrT_hi; md.Bl[2]=zrT_lo;
    md.Dout[2]=a3; md.Dhi[2]=nullptr; md.Dlo[2]=nullptr;
    md.sA[2]=0; md.sB[2]=TS; md.sD[2]=FT; md.N[2]=T_; md.gxlog[2]=3; md.epi[2]=EPI_NONE;

    mma_multi<<<3 * B_ * 32, 256, GEMM_SMEM>>>(md);

    // G2: C[t][h] = tanh( sum_s zrT[t][s] * auxT[h][s] )   M=N=1024, K=512
    mma_gemm<EPI_TANH_HILO, 512><<<dim3(T_/BN, T_/BM, B_), 256, GEMM_SMEM>>>(
        zrT_hi, zrT_lo, auxT_hi, auxT_lo, Cmat, C_hi, C_lo, nullptr, nullptr,
        T_, TS, TS, TT, 0L);

    // G5 fused: logits[b,t] = sum_f w_hq[f]*tanh(a3[f,t] + sum_h a2[f,h]*C[t,h])
    mma_gemm<EPI_WG_RED, 1024><<<dim3(T_/BN, F_/BM, B_), 256, GEMM_SMEM>>>(
        a2_hi, a2_lo, C_hi, C_lo, nullptr, nullptr, nullptr, a3, whq,
        T_, FT, TT, 0L, FT);

    softmax_k<<<B_, 256>>>(aq);
    attn_k<<<(B_ * S_ * 32) / 256, 256>>>(zr, aq, attn);
}